// round 4
// baseline (speedup 1.0000x reference)
#include <cuda_runtime.h>
#include <cuda_bf16.h>
#include <math.h>
#include <stdint.h>

#define BATCH 4
#define SEQ   2048
#define HID   1024
#define MTOT  (BATCH * SEQ)   // 8192

// ---------------------------------------------------------------------------
// Scratch (device globals; allocation-free per harness rules)
// ---------------------------------------------------------------------------
__device__ __nv_bfloat16 g_Xh[(size_t)MTOT * HID];
__device__ __nv_bfloat16 g_Xl[(size_t)MTOT * HID];

__device__ __nv_bfloat16 g_Wqh[HID * HID], g_Wql[HID * HID];
__device__ __nv_bfloat16 g_Wkh[HID * HID], g_Wkl[HID * HID];
__device__ __nv_bfloat16 g_Wvh[HID * HID], g_Wvl[HID * HID];
__device__ __nv_bfloat16 g_Whh[HID * HID], g_Whl[HID * HID];

__device__ __nv_bfloat16 g_Qh[(size_t)MTOT * HID], g_Ql[(size_t)MTOT * HID];
__device__ __nv_bfloat16 g_Kh[(size_t)MTOT * HID], g_Kl[(size_t)MTOT * HID];
__device__ float         g_Vf[(size_t)MTOT * HID];
__device__ __nv_bfloat16 g_Vth[(size_t)MTOT * HID], g_Vtl[(size_t)MTOT * HID];

__device__ float         g_Sf[(size_t)BATCH * SEQ * SEQ];
__device__ __nv_bfloat16 g_Sh[(size_t)BATCH * SEQ * SEQ], g_Sl[(size_t)BATCH * SEQ * SEQ];

__device__ __nv_bfloat16 g_Ch[(size_t)MTOT * HID], g_Cl[(size_t)MTOT * HID];

// ---------------------------------------------------------------------------
// helpers
// ---------------------------------------------------------------------------
__device__ __forceinline__ uint32_t smem_u32(const void* p) {
    uint32_t a;
    asm("{ .reg .u64 t; cvta.to.shared.u64 t, %1; cvt.u32.u64 %0, t; }"
        : "=r"(a) : "l"(p));
    return a;
}

__device__ __forceinline__ void cp16(uint32_t saddr, const void* gaddr) {
    asm volatile("cp.async.cg.shared.global [%0], [%1], 16;"
                 :: "r"(saddr), "l"(gaddr));
}
__device__ __forceinline__ void cp_commit() {
    asm volatile("cp.async.commit_group;" ::: "memory");
}
template <int N>
__device__ __forceinline__ void cp_wait() {
    asm volatile("cp.async.wait_group %0;" :: "n"(N) : "memory");
}

__device__ __forceinline__ void ldsm4(uint32_t addr, uint32_t& r0, uint32_t& r1,
                                      uint32_t& r2, uint32_t& r3) {
    asm volatile("ldmatrix.sync.aligned.m8n8.x4.shared.b16 {%0,%1,%2,%3}, [%4];"
                 : "=r"(r0), "=r"(r1), "=r"(r2), "=r"(r3) : "r"(addr));
}

__device__ __forceinline__ void mma16816(float* c, const uint32_t* a,
                                         uint32_t b0, uint32_t b1) {
    asm volatile(
        "mma.sync.aligned.m16n8k16.row.col.f32.bf16.bf16.f32 "
        "{%0,%1,%2,%3}, {%4,%5,%6,%7}, {%8,%9}, {%0,%1,%2,%3};"
        : "+f"(c[0]), "+f"(c[1]), "+f"(c[2]), "+f"(c[3])
        : "r"(a[0]), "r"(a[1]), "r"(a[2]), "r"(a[3]), "r"(b0), "r"(b1));
}

__device__ __forceinline__ void split2(float x, __nv_bfloat16& h, __nv_bfloat16& l) {
    h = __float2bfloat16(x);
    l = __float2bfloat16(x - __bfloat162float(h));
}

// ldmatrix x4 source address inside a [128 rows x 64B] swizzled tile.
__device__ __forceinline__ uint32_t lds_addr(uint32_t tb, int base_row, int ks, int lane) {
    int r = base_row + ((lane >> 3) & 1) * 8 + (lane & 7);
    int c = (ks * 2 + (lane >> 4)) ^ ((r >> 1) & 3);
    return tb + (uint32_t)(r * 64 + c * 16);
}

// ---------------------------------------------------------------------------
// Emulated-fp32 NT GEMM via 3x bf16 mma.sync:
//   C[M,N] = alpha*(A @ B^T) + bias;  A:[M,K] hi/lo, B:[N,K] hi/lo (K-major)
// Block 128x128, Ktile 32, 8 warps (64x32 warp tile).
// 3-stage cp.async ring, one __syncthreads per K-tile, always-commit pattern.
// ---------------------------------------------------------------------------
#define STAGE_BYTES 32768u
#define GEMM_SMEM   98304   // 3 stages * 4 tiles * 8KB

template <bool SPLITOUT>
__global__ __launch_bounds__(256) void gemm_mma(
    const __nv_bfloat16* __restrict__ Ahp, const __nv_bfloat16* __restrict__ Alp,
    const __nv_bfloat16* __restrict__ Bhp, const __nv_bfloat16* __restrict__ Blp,
    const float* __restrict__ bias,
    float* __restrict__ Cf, __nv_bfloat16* __restrict__ Ch, __nv_bfloat16* __restrict__ Cl,
    int N, int K, size_t sA, size_t sB, size_t sC, float alpha)
{
    extern __shared__ char smem_raw[];
    const uint32_t smem = smem_u32(smem_raw);

    const int tid  = threadIdx.x;
    const int lane = tid & 31;
    const int warp = tid >> 5;
    const int wm = warp >> 2;          // 0..1  (M)
    const int wn = warp & 3;           // 0..3  (N)
    const int bn = blockIdx.x, bm = blockIdx.y, z = blockIdx.z;

    const __nv_bfloat16* pAh = Ahp + (size_t)z * sA + (size_t)bm * 128 * K;
    const __nv_bfloat16* pAl = Alp + (size_t)z * sA + (size_t)bm * 128 * K;
    const __nv_bfloat16* pBh = Bhp + (size_t)z * sB + (size_t)bn * 128 * K;
    const __nv_bfloat16* pBl = Blp + (size_t)z * sB + (size_t)bn * 128 * K;

    // per-thread cp.async mapping: 8 x 16B chunks per stage (2 per tile)
    auto stage_load = [&](uint32_t sb, int k0) {
#pragma unroll
        for (int h = 0; h < 2; ++h) {
            const int ch  = tid + h * 256;
            const int row = ch >> 2, c = ch & 3;
            const int cs  = c ^ ((row >> 1) & 3);
            const uint32_t so = (uint32_t)(row * 64 + cs * 16);
            const size_t   go = (size_t)row * K + k0 + c * 8;
            cp16(sb +     0 + so, pAh + go);
            cp16(sb +  8192 + so, pAl + go);
            cp16(sb + 16384 + so, pBh + go);
            cp16(sb + 24576 + so, pBl + go);
        }
    };

    float acc[4][4][4];
#pragma unroll
    for (int i = 0; i < 4; ++i)
#pragma unroll
        for (int j = 0; j < 4; ++j)
#pragma unroll
            for (int q = 0; q < 4; ++q) acc[i][j][q] = 0.f;

    const int KT = K >> 5;   // >= 2 always (K = 1024 or 2048)

    // prologue: stages 0 and 1 in flight (2 groups pending)
    stage_load(smem, 0);
    cp_commit();
    stage_load(smem + STAGE_BYTES, 32);
    cp_commit();

    int buf = 0;   // buffer index of stage kt
    for (int kt = 0; kt < KT; ++kt) {
        cp_wait<1>();        // stage kt landed (pending <= 1)
        __syncthreads();     // visible to all; previous stage fully consumed

        // keep exactly 2 groups in flight (empty commit near the tail)
        if (kt + 2 < KT) {
            int nbuf = buf + 2; if (nbuf >= 3) nbuf -= 3;
            stage_load(smem + (uint32_t)nbuf * STAGE_BYTES, (kt + 2) * 32);
        }
        cp_commit();

        const uint32_t sb = smem + (uint32_t)buf * STAGE_BYTES;
#pragma unroll
        for (int ks = 0; ks < 2; ++ks) {
            uint32_t aH[4][4], aL[4][4], bH[4][2], bL[4][2];
#pragma unroll
            for (int i = 0; i < 4; ++i)
                ldsm4(lds_addr(sb, wm * 64 + i * 16, ks, lane),
                      aH[i][0], aH[i][1], aH[i][2], aH[i][3]);
#pragma unroll
            for (int j2 = 0; j2 < 2; ++j2) {
                uint32_t r0, r1, r2, r3;
                ldsm4(lds_addr(sb + 16384, wn * 32 + j2 * 16, ks, lane), r0, r1, r2, r3);
                bH[j2 * 2 + 0][0] = r0; bH[j2 * 2 + 0][1] = r2;
                bH[j2 * 2 + 1][0] = r1; bH[j2 * 2 + 1][1] = r3;
                ldsm4(lds_addr(sb + 24576, wn * 32 + j2 * 16, ks, lane), r0, r1, r2, r3);
                bL[j2 * 2 + 0][0] = r0; bL[j2 * 2 + 0][1] = r2;
                bL[j2 * 2 + 1][0] = r1; bL[j2 * 2 + 1][1] = r3;
            }
#pragma unroll
            for (int i = 0; i < 4; ++i)
#pragma unroll
                for (int j = 0; j < 4; ++j) {
                    mma16816(acc[i][j], aH[i], bH[j][0], bH[j][1]);
                    mma16816(acc[i][j], aH[i], bL[j][0], bL[j][1]);
                }
#pragma unroll
            for (int i = 0; i < 4; ++i)
                ldsm4(lds_addr(sb + 8192, wm * 64 + i * 16, ks, lane),
                      aL[i][0], aL[i][1], aL[i][2], aL[i][3]);
#pragma unroll
            for (int i = 0; i < 4; ++i)
#pragma unroll
                for (int j = 0; j < 4; ++j)
                    mma16816(acc[i][j], aL[i], bH[j][0], bH[j][1]);
        }
        if (++buf == 3) buf = 0;
    }

    // epilogue
    const size_t growb = (size_t)bm * 128 + wm * 64;
    const int    gcolb = bn * 128 + wn * 32;
#pragma unroll
    for (int i = 0; i < 4; ++i) {
        const size_t r0 = growb + i * 16 + (lane >> 2);
#pragma unroll
        for (int j = 0; j < 4; ++j) {
            const int col = gcolb + j * 8 + (lane & 3) * 2;
            float b0 = 0.f, b1 = 0.f;
            if (bias) { b0 = bias[col]; b1 = bias[col + 1]; }
            const float v00 = acc[i][j][0] * alpha + b0;
            const float v01 = acc[i][j][1] * alpha + b1;
            const float v10 = acc[i][j][2] * alpha + b0;
            const float v11 = acc[i][j][3] * alpha + b1;
            const size_t o0 = (size_t)z * sC + r0 * N + col;
            const size_t o1 = o0 + (size_t)8 * N;
            if (SPLITOUT) {
                __nv_bfloat16 h0, l0, h1, l1;
                split2(v00, h0, l0); split2(v01, h1, l1);
                *reinterpret_cast<__nv_bfloat162*>(Ch + o0) = __nv_bfloat162(h0, h1);
                *reinterpret_cast<__nv_bfloat162*>(Cl + o0) = __nv_bfloat162(l0, l1);
                split2(v10, h0, l0); split2(v11, h1, l1);
                *reinterpret_cast<__nv_bfloat162*>(Ch + o1) = __nv_bfloat162(h0, h1);
                *reinterpret_cast<__nv_bfloat162*>(Cl + o1) = __nv_bfloat162(l0, l1);
            } else {
                *reinterpret_cast<float2*>(Cf + o0) = make_float2(v00, v01);
                *reinterpret_cast<float2*>(Cf + o1) = make_float2(v10, v11);
            }
        }
    }
}

// ---------------------------------------------------------------------------
// fp32 -> (hi, lo) bf16 split, vectorized by 4
// ---------------------------------------------------------------------------
__global__ __launch_bounds__(256) void split_f32(
    const float4* __restrict__ in, __nv_bfloat16* __restrict__ h,
    __nv_bfloat16* __restrict__ l, size_t n4)
{
    size_t i = (size_t)blockIdx.x * blockDim.x + threadIdx.x;
    if (i >= n4) return;
    float4 v = in[i];
    __align__(8) __nv_bfloat16 hb[4], lb[4];
    split2(v.x, hb[0], lb[0]);
    split2(v.y, hb[1], lb[1]);
    split2(v.z, hb[2], lb[2]);
    split2(v.w, hb[3], lb[3]);
    reinterpret_cast<uint2*>(h)[i] = *reinterpret_cast<uint2*>(hb);
    reinterpret_cast<uint2*>(l)[i] = *reinterpret_cast<uint2*>(lb);
}

// ---------------------------------------------------------------------------
// Generic transpose + split: in [R,C] fp32 -> out hi/lo [C,R] bf16 (z-batched)
// ---------------------------------------------------------------------------
__global__ __launch_bounds__(256) void transpose_split(
    const float* __restrict__ in, __nv_bfloat16* __restrict__ hT,
    __nv_bfloat16* __restrict__ lT, int R, int C)
{
    __shared__ float t[32][33];
    const size_t zoff = (size_t)blockIdx.z * R * C;
    const int r0 = blockIdx.y * 32, c0 = blockIdx.x * 32;
    const int tx = threadIdx.x, ty = threadIdx.y;   // (32, 8)
#pragma unroll
    for (int j = 0; j < 4; ++j)
        t[ty + 8 * j][tx] = in[zoff + (size_t)(r0 + ty + 8 * j) * C + c0 + tx];
    __syncthreads();
#pragma unroll
    for (int j = 0; j < 4; ++j) {
        float v = t[tx][ty + 8 * j];
        __nv_bfloat16 h, l;
        split2(v, h, l);
        size_t o = zoff + (size_t)(c0 + ty + 8 * j) * R + r0 + tx;
        hT[o] = h;
        lT[o] = l;
    }
}

// ---------------------------------------------------------------------------
// All 4 weight transposes in ONE launch (z selects the weight).
// ---------------------------------------------------------------------------
__global__ __launch_bounds__(256) void transpose_weights(
    const float* __restrict__ W0, const float* __restrict__ W1,
    const float* __restrict__ W2, const float* __restrict__ W3,
    __nv_bfloat16* __restrict__ H0, __nv_bfloat16* __restrict__ L0,
    __nv_bfloat16* __restrict__ H1, __nv_bfloat16* __restrict__ L1,
    __nv_bfloat16* __restrict__ H2, __nv_bfloat16* __restrict__ L2,
    __nv_bfloat16* __restrict__ H3, __nv_bfloat16* __restrict__ L3)
{
    __shared__ float t[32][33];
    const int zi = blockIdx.z;
    const float* in = (zi == 0) ? W0 : (zi == 1) ? W1 : (zi == 2) ? W2 : W3;
    __nv_bfloat16* hT = (zi == 0) ? H0 : (zi == 1) ? H1 : (zi == 2) ? H2 : H3;
    __nv_bfloat16* lT = (zi == 0) ? L0 : (zi == 1) ? L1 : (zi == 2) ? L2 : L3;

    const int r0 = blockIdx.y * 32, c0 = blockIdx.x * 32;
    const int tx = threadIdx.x, ty = threadIdx.y;   // (32, 8)
#pragma unroll
    for (int j = 0; j < 4; ++j)
        t[ty + 8 * j][tx] = in[(size_t)(r0 + ty + 8 * j) * HID + c0 + tx];
    __syncthreads();
#pragma unroll
    for (int j = 0; j < 4; ++j) {
        float v = t[tx][ty + 8 * j];
        __nv_bfloat16 h, l;
        split2(v, h, l);
        size_t o = (size_t)(c0 + ty + 8 * j) * HID + r0 + tx;
        hT[o] = h;
        lT[o] = l;
    }
}

// ---------------------------------------------------------------------------
// Row softmax over 2048 cols, fp32 in, split bf16 out.
// ---------------------------------------------------------------------------
__global__ __launch_bounds__(256) void softmax_split(
    const float* __restrict__ Sf, __nv_bfloat16* __restrict__ Sh,
    __nv_bfloat16* __restrict__ Sl)
{
    const size_t base = (size_t)blockIdx.x * SEQ;
    const int tid = threadIdx.x;

    float v[8];
    float m = -INFINITY;
#pragma unroll
    for (int i = 0; i < 8; ++i) {
        v[i] = Sf[base + tid + i * 256];
        m = fmaxf(m, v[i]);
    }

    __shared__ float red[256];
    red[tid] = m;
    __syncthreads();
#pragma unroll
    for (int s = 128; s > 0; s >>= 1) {
        if (tid < s) red[tid] = fmaxf(red[tid], red[tid + s]);
        __syncthreads();
    }
    m = red[0];
    __syncthreads();

    float sum = 0.f;
#pragma unroll
    for (int i = 0; i < 8; ++i) {
        v[i] = expf(v[i] - m);
        sum += v[i];
    }
    red[tid] = sum;
    __syncthreads();
#pragma unroll
    for (int s = 128; s > 0; s >>= 1) {
        if (tid < s) red[tid] += red[tid + s];
        __syncthreads();
    }
    const float inv = 1.0f / red[0];
#pragma unroll
    for (int i = 0; i < 8; ++i) {
        float p = v[i] * inv;
        __nv_bfloat16 h, l;
        split2(p, h, l);
        Sh[base + tid + i * 256] = h;
        Sl[base + tid + i * 256] = l;
    }
}

// ---------------------------------------------------------------------------
extern "C" void kernel_launch(void* const* d_in, const int* in_sizes, int n_in,
                              void* d_out, int out_size)
{
    (void)in_sizes; (void)n_in; (void)out_size;

    const float* X  = (const float*)d_in[0];
    const float* Wq = (const float*)d_in[1];
    const float* bq = (const float*)d_in[2];
    const float* Wk = (const float*)d_in[3];
    const float* bk = (const float*)d_in[4];
    const float* Wv = (const float*)d_in[5];
    const float* bv = (const float*)d_in[6];
    const float* Wh = (const float*)d_in[7];
    const float* bh = (const float*)d_in[8];
    float* out = (float*)d_out;

    __nv_bfloat16 *Xh, *Xl, *Wqh, *Wql, *Wkh, *Wkl, *Wvh, *Wvl, *Whh, *Whl;
    __nv_bfloat16 *Qh, *Ql, *Kh, *Kl, *Vth, *Vtl, *Sh, *Sl, *Ch, *Cl;
    float *Vf, *Sf;
    cudaGetSymbolAddress((void**)&Xh,  g_Xh);  cudaGetSymbolAddress((void**)&Xl,  g_Xl);
    cudaGetSymbolAddress((void**)&Wqh, g_Wqh); cudaGetSymbolAddress((void**)&Wql, g_Wql);
    cudaGetSymbolAddress((void**)&Wkh, g_Wkh); cudaGetSymbolAddress((void**)&Wkl, g_Wkl);
    cudaGetSymbolAddress((void**)&Wvh, g_Wvh); cudaGetSymbolAddress((void**)&Wvl, g_Wvl);
    cudaGetSymbolAddress((void**)&Whh, g_Whh); cudaGetSymbolAddress((void**)&Whl, g_Whl);
    cudaGetSymbolAddress((void**)&Qh,  g_Qh);  cudaGetSymbolAddress((void**)&Ql,  g_Ql);
    cudaGetSymbolAddress((void**)&Kh,  g_Kh);  cudaGetSymbolAddress((void**)&Kl,  g_Kl);
    cudaGetSymbolAddress((void**)&Vf,  g_Vf);
    cudaGetSymbolAddress((void**)&Vth, g_Vth); cudaGetSymbolAddress((void**)&Vtl, g_Vtl);
    cudaGetSymbolAddress((void**)&Sf,  g_Sf);
    cudaGetSymbolAddress((void**)&Sh,  g_Sh);  cudaGetSymbolAddress((void**)&Sl,  g_Sl);
    cudaGetSymbolAddress((void**)&Ch,  g_Ch);  cudaGetSymbolAddress((void**)&Cl,  g_Cl);

    cudaFuncSetAttribute(gemm_mma<true>,  cudaFuncAttributeMaxDynamicSharedMemorySize, GEMM_SMEM);
    cudaFuncSetAttribute(gemm_mma<false>, cudaFuncAttributeMaxDynamicSharedMemorySize, GEMM_SMEM);

    const dim3 blk(256);
    const float scale = 1.0f / 32.0f;   // 1/sqrt(1024)

    // launch 0: split X
    split_f32<<<(MTOT * HID / 4 + 255) / 256, blk>>>(
        (const float4*)X, Xh, Xl, (size_t)MTOT * HID / 4);

    // launch 1: all 4 weight transposes (z-batched)
    dim3 tgw(HID / 32, HID / 32, 4), tblk(32, 8);
    transpose_weights<<<tgw, tblk>>>(Wq, Wk, Wv, Wh,
                                     Wqh, Wql, Wkh, Wkl, Wvh, Wvl, Whh, Whl);

    // launches 2-4: projections (M=8192, N=1024, K=1024)
    dim3 gp(HID / 128, MTOT / 128, 1);
    gemm_mma<true ><<<gp, blk, GEMM_SMEM>>>(Xh, Xl, Wqh, Wql, bq, nullptr, Qh, Ql,
                                            HID, HID, 0, 0, 0, 1.f);
    gemm_mma<true ><<<gp, blk, GEMM_SMEM>>>(Xh, Xl, Wkh, Wkl, bk, nullptr, Kh, Kl,
                                            HID, HID, 0, 0, 0, 1.f);
    gemm_mma<false><<<gp, blk, GEMM_SMEM>>>(Xh, Xl, Wvh, Wvl, bv, Vf, nullptr, nullptr,
                                            HID, HID, 0, 0, 0, 1.f);

    // launch 5 (ncu -s 5 target): scores = scale * Q @ K^T (batched) -> fp32
    dim3 gs(SEQ / 128, SEQ / 128, BATCH);
    gemm_mma<false><<<gs, blk, GEMM_SMEM>>>(Qh, Ql, Kh, Kl, nullptr, Sf, nullptr, nullptr,
                                            SEQ, HID,
                                            (size_t)SEQ * HID, (size_t)SEQ * HID,
                                            (size_t)SEQ * SEQ, scale);

    // launch 6: V -> V^T (per batch) with split (needs only V)
    dim3 tgv(HID / 32, SEQ / 32, BATCH);
    transpose_split<<<tgv, tblk>>>(Vf, Vth, Vtl, SEQ, HID);

    // launch 7: softmax + split
    softmax_split<<<BATCH * SEQ, blk>>>(Sf, Sh, Sl);

    // launch 8: context = attn @ V (batched, K=2048) -> split
    dim3 gc(HID / 128, SEQ / 128, BATCH);
    gemm_mma<true ><<<gc, blk, GEMM_SMEM>>>(Sh, Sl, Vth, Vtl, nullptr, nullptr, Ch, Cl,
                                            HID, SEQ,
                                            (size_t)SEQ * SEQ, (size_t)HID * SEQ,
                                            (size_t)SEQ * HID, 1.f);

    // launch 9: y = context @ Wh + bh -> d_out fp32
    dim3 go(HID / 128, MTOT / 128, 1);
    gemm_mma<false><<<go, blk, GEMM_SMEM>>>(Ch, Cl, Whh, Whl, bh, out, nullptr, nullptr,
                                            HID, HID, 0, 0, 0, 1.f);
}

// round 6
// speedup vs baseline: 1.5405x; 1.5405x over previous
#include <cuda_runtime.h>
#include <cuda_fp16.h>
#include <math.h>
#include <stdint.h>

#define BATCH 4
#define SEQ   2048
#define HID   1024
#define MTOT  (BATCH * SEQ)   // 8192

// ---------------------------------------------------------------------------
// Scratch (device globals; allocation-free per harness rules)
// ---------------------------------------------------------------------------
__device__ __half g_Xh[(size_t)MTOT * HID];

__device__ __half g_Wqh[HID * HID], g_Wql[HID * HID];
__device__ __half g_Wkh[HID * HID], g_Wkl[HID * HID];
__device__ __half g_Wvh[HID * HID], g_Wvl[HID * HID];
__device__ __half g_Whh[HID * HID], g_Whl[HID * HID];

__device__ __half g_Qh[(size_t)MTOT * HID];
__device__ __half g_Kh[(size_t)MTOT * HID], g_Kl[(size_t)MTOT * HID];
__device__ float  g_Vf[(size_t)MTOT * HID];
__device__ __half g_Vth[(size_t)MTOT * HID], g_Vtl[(size_t)MTOT * HID];

__device__ float  g_Sf[(size_t)BATCH * SEQ * SEQ];
__device__ __half g_Sh[(size_t)BATCH * SEQ * SEQ];

__device__ __half g_Ch[(size_t)MTOT * HID];

// ---------------------------------------------------------------------------
// helpers
// ---------------------------------------------------------------------------
__device__ __forceinline__ uint32_t smem_u32(const void* p) {
    uint32_t a;
    asm("{ .reg .u64 t; cvta.to.shared.u64 t, %1; cvt.u32.u64 %0, t; }"
        : "=r"(a) : "l"(p));
    return a;
}

__device__ __forceinline__ void cp16(uint32_t saddr, const void* gaddr) {
    asm volatile("cp.async.cg.shared.global [%0], [%1], 16;"
                 :: "r"(saddr), "l"(gaddr));
}
__device__ __forceinline__ void cp_commit() {
    asm volatile("cp.async.commit_group;" ::: "memory");
}
template <int N>
__device__ __forceinline__ void cp_wait() {
    asm volatile("cp.async.wait_group %0;" :: "n"(N) : "memory");
}

__device__ __forceinline__ void ldsm4(uint32_t addr, uint32_t& r0, uint32_t& r1,
                                      uint32_t& r2, uint32_t& r3) {
    asm volatile("ldmatrix.sync.aligned.m8n8.x4.shared.b16 {%0,%1,%2,%3}, [%4];"
                 : "=r"(r0), "=r"(r1), "=r"(r2), "=r"(r3) : "r"(addr));
}

__device__ __forceinline__ void mma16816(float* c, const uint32_t* a,
                                         uint32_t b0, uint32_t b1) {
    asm volatile(
        "mma.sync.aligned.m16n8k16.row.col.f32.f16.f16.f32 "
        "{%0,%1,%2,%3}, {%4,%5,%6,%7}, {%8,%9}, {%0,%1,%2,%3};"
        : "+f"(c[0]), "+f"(c[1]), "+f"(c[2]), "+f"(c[3])
        : "r"(a[0]), "r"(a[1]), "r"(a[2]), "r"(a[3]), "r"(b0), "r"(b1));
}

__device__ __forceinline__ void split2h(float x, __half& h, __half& l) {
    h = __float2half_rn(x);
    l = __float2half_rn(x - __half2float(h));
}

// ldmatrix x4 source address inside a [128 rows x 64B] swizzled tile.
__device__ __forceinline__ uint32_t lds_addr(uint32_t tb, int base_row, int ks, int lane) {
    int r = base_row + ((lane >> 3) & 1) * 8 + (lane & 7);
    int c = (ks * 2 + (lane >> 4)) ^ ((r >> 1) & 3);
    return tb + (uint32_t)(r * 64 + c * 16);
}

// ---------------------------------------------------------------------------
// Emulated-fp32 NT GEMM via 2x fp16 mma.sync:
//   C[M,N] = alpha*(A @ B^T) + bias;  A:[M,K] fp16 hi; B:[N,K] fp16 hi+lo
// Block 128x128, Ktile 32, 8 warps (64x32 warp tile), 2-stage cp.async ring
// (R3-proven schedule: issue next-stage loads BEFORE waiting).
// OUTMODE: 0 = fp32, 1 = fp16 single, 2 = fp16 hi+lo pair.
// ---------------------------------------------------------------------------
#define STAGE_BYTES 24576u
#define GEMM_SMEM   49152   // 2 stages * 3 tiles * 8KB

template <int OUTMODE>
__global__ __launch_bounds__(256) void gemm_h(
    const __half* __restrict__ Ap,
    const __half* __restrict__ Bhp, const __half* __restrict__ Blp,
    const float* __restrict__ bias,
    float* __restrict__ Cf, __half* __restrict__ Ch, __half* __restrict__ Cl,
    int N, int K, size_t sA, size_t sB, size_t sC, float alpha)
{
    extern __shared__ char smem_raw[];
    const uint32_t smem = smem_u32(smem_raw);

    const int tid  = threadIdx.x;
    const int lane = tid & 31;
    const int warp = tid >> 5;
    const int wm = warp >> 2;          // 0..1  (M)
    const int wn = warp & 3;           // 0..3  (N)
    const int bn = blockIdx.x, bm = blockIdx.y, z = blockIdx.z;

    const __half* pA  = Ap  + (size_t)z * sA + (size_t)bm * 128 * K;
    const __half* pBh = Bhp + (size_t)z * sB + (size_t)bn * 128 * K;
    const __half* pBl = Blp + (size_t)z * sB + (size_t)bn * 128 * K;

    // per-thread cp.async mapping: 6 x 16B chunks per stage (2 per tile)
    auto stage_load = [&](uint32_t sb, int k0) {
#pragma unroll
        for (int h = 0; h < 2; ++h) {
            const int ch  = tid + h * 256;
            const int row = ch >> 2, c = ch & 3;
            const int cs  = c ^ ((row >> 1) & 3);
            const uint32_t so = (uint32_t)(row * 64 + cs * 16);
            const size_t   go = (size_t)row * K + k0 + c * 8;
            cp16(sb +     0 + so, pA  + go);
            cp16(sb +  8192 + so, pBh + go);
            cp16(sb + 16384 + so, pBl + go);
        }
    };

    float acc[4][4][4];
#pragma unroll
    for (int i = 0; i < 4; ++i)
#pragma unroll
        for (int j = 0; j < 4; ++j)
#pragma unroll
            for (int q = 0; q < 4; ++q) acc[i][j][q] = 0.f;

    const int KT = K >> 5;

    stage_load(smem, 0);
    cp_commit();

    for (int kt = 0; kt < KT; ++kt) {
        // issue next stage FIRST (loads in flight while waiting), then wait
        if (kt + 1 < KT) {
            stage_load(smem + (uint32_t)((kt + 1) & 1) * STAGE_BYTES, (kt + 1) * 32);
            cp_commit();
            cp_wait<1>();
        } else {
            cp_wait<0>();
        }
        __syncthreads();

        const uint32_t sb = smem + (uint32_t)(kt & 1) * STAGE_BYTES;
#pragma unroll
        for (int ks = 0; ks < 2; ++ks) {
            uint32_t aH[4][4], bH[4][2], bL[4][2];
#pragma unroll
            for (int i = 0; i < 4; ++i)
                ldsm4(lds_addr(sb, wm * 64 + i * 16, ks, lane),
                      aH[i][0], aH[i][1], aH[i][2], aH[i][3]);
#pragma unroll
            for (int j2 = 0; j2 < 2; ++j2) {
                uint32_t r0, r1, r2, r3;
                ldsm4(lds_addr(sb + 8192, wn * 32 + j2 * 16, ks, lane), r0, r1, r2, r3);
                bH[j2 * 2 + 0][0] = r0; bH[j2 * 2 + 0][1] = r2;
                bH[j2 * 2 + 1][0] = r1; bH[j2 * 2 + 1][1] = r3;
                ldsm4(lds_addr(sb + 16384, wn * 32 + j2 * 16, ks, lane), r0, r1, r2, r3);
                bL[j2 * 2 + 0][0] = r0; bL[j2 * 2 + 0][1] = r2;
                bL[j2 * 2 + 1][0] = r1; bL[j2 * 2 + 1][1] = r3;
            }
#pragma unroll
            for (int i = 0; i < 4; ++i)
#pragma unroll
                for (int j = 0; j < 4; ++j) {
                    mma16816(acc[i][j], aH[i], bH[j][0], bH[j][1]);
                    mma16816(acc[i][j], aH[i], bL[j][0], bL[j][1]);
                }
        }
        __syncthreads();
    }

    // epilogue
    const size_t growb = (size_t)bm * 128 + wm * 64;
    const int    gcolb = bn * 128 + wn * 32;
#pragma unroll
    for (int i = 0; i < 4; ++i) {
        const size_t r0 = growb + i * 16 + (lane >> 2);
#pragma unroll
        for (int j = 0; j < 4; ++j) {
            const int col = gcolb + j * 8 + (lane & 3) * 2;
            float b0 = 0.f, b1 = 0.f;
            if (bias) { b0 = bias[col]; b1 = bias[col + 1]; }
            const float v00 = acc[i][j][0] * alpha + b0;
            const float v01 = acc[i][j][1] * alpha + b1;
            const float v10 = acc[i][j][2] * alpha + b0;
            const float v11 = acc[i][j][3] * alpha + b1;
            const size_t o0 = (size_t)z * sC + r0 * N + col;
            const size_t o1 = o0 + (size_t)8 * N;
            if (OUTMODE == 0) {
                *reinterpret_cast<float2*>(Cf + o0) = make_float2(v00, v01);
                *reinterpret_cast<float2*>(Cf + o1) = make_float2(v10, v11);
            } else if (OUTMODE == 1) {
                *reinterpret_cast<__half2*>(Ch + o0) =
                    __halves2half2(__float2half_rn(v00), __float2half_rn(v01));
                *reinterpret_cast<__half2*>(Ch + o1) =
                    __halves2half2(__float2half_rn(v10), __float2half_rn(v11));
            } else {
                __half h0, l0, h1, l1;
                split2h(v00, h0, l0); split2h(v01, h1, l1);
                *reinterpret_cast<__half2*>(Ch + o0) = __halves2half2(h0, h1);
                *reinterpret_cast<__half2*>(Cl + o0) = __halves2half2(l0, l1);
                split2h(v10, h0, l0); split2h(v11, h1, l1);
                *reinterpret_cast<__half2*>(Ch + o1) = __halves2half2(h0, h1);
                *reinterpret_cast<__half2*>(Cl + o1) = __halves2half2(l0, l1);
            }
        }
    }
}

// ---------------------------------------------------------------------------
// fp32 -> fp16 hi-only convert (for X), vectorized by 4
// ---------------------------------------------------------------------------
__global__ __launch_bounds__(256) void to_half(
    const float4* __restrict__ in, __half* __restrict__ h, size_t n4)
{
    size_t i = (size_t)blockIdx.x * blockDim.x + threadIdx.x;
    if (i >= n4) return;
    float4 v = in[i];
    __align__(8) __half hb[4];
    hb[0] = __float2half_rn(v.x);
    hb[1] = __float2half_rn(v.y);
    hb[2] = __float2half_rn(v.z);
    hb[3] = __float2half_rn(v.w);
    reinterpret_cast<uint2*>(h)[i] = *reinterpret_cast<uint2*>(hb);
}

// ---------------------------------------------------------------------------
// Generic transpose + split: in [R,C] fp32 -> hi/lo fp16 [C,R] (z-batched)
// ---------------------------------------------------------------------------
__global__ __launch_bounds__(256) void transpose_split(
    const float* __restrict__ in, __half* __restrict__ hT,
    __half* __restrict__ lT, int R, int C)
{
    __shared__ float t[32][33];
    const size_t zoff = (size_t)blockIdx.z * R * C;
    const int r0 = blockIdx.y * 32, c0 = blockIdx.x * 32;
    const int tx = threadIdx.x, ty = threadIdx.y;   // (32, 8)
#pragma unroll
    for (int j = 0; j < 4; ++j)
        t[ty + 8 * j][tx] = in[zoff + (size_t)(r0 + ty + 8 * j) * C + c0 + tx];
    __syncthreads();
#pragma unroll
    for (int j = 0; j < 4; ++j) {
        float v = t[tx][ty + 8 * j];
        __half h, l;
        split2h(v, h, l);
        size_t o = zoff + (size_t)(c0 + ty + 8 * j) * R + r0 + tx;
        hT[o] = h;
        lT[o] = l;
    }
}

// ---------------------------------------------------------------------------
// All 4 weight transposes in ONE launch (z selects the weight).
// ---------------------------------------------------------------------------
__global__ __launch_bounds__(256) void transpose_weights(
    const float* __restrict__ W0, const float* __restrict__ W1,
    const float* __restrict__ W2, const float* __restrict__ W3,
    __half* __restrict__ H0, __half* __restrict__ L0,
    __half* __restrict__ H1, __half* __restrict__ L1,
    __half* __restrict__ H2, __half* __restrict__ L2,
    __half* __restrict__ H3, __half* __restrict__ L3)
{
    __shared__ float t[32][33];
    const int zi = blockIdx.z;
    const float* in = (zi == 0) ? W0 : (zi == 1) ? W1 : (zi == 2) ? W2 : W3;
    __half* hT = (zi == 0) ? H0 : (zi == 1) ? H1 : (zi == 2) ? H2 : H3;
    __half* lT = (zi == 0) ? L0 : (zi == 1) ? L1 : (zi == 2) ? L2 : L3;

    const int r0 = blockIdx.y * 32, c0 = blockIdx.x * 32;
    const int tx = threadIdx.x, ty = threadIdx.y;   // (32, 8)
#pragma unroll
    for (int j = 0; j < 4; ++j)
        t[ty + 8 * j][tx] = in[(size_t)(r0 + ty + 8 * j) * HID + c0 + tx];
    __syncthreads();
#pragma unroll
    for (int j = 0; j < 4; ++j) {
        float v = t[tx][ty + 8 * j];
        __half h, l;
        split2h(v, h, l);
        size_t o = (size_t)(c0 + ty + 8 * j) * HID + r0 + tx;
        hT[o] = h;
        lT[o] = l;
    }
}

// ---------------------------------------------------------------------------
// Row softmax over 2048 cols, fp32 in, fp16 out.
// ---------------------------------------------------------------------------
__global__ __launch_bounds__(256) void softmax_h(
    const float* __restrict__ Sf, __half* __restrict__ Sh)
{
    const size_t base = (size_t)blockIdx.x * SEQ;
    const int tid = threadIdx.x;

    float v[8];
    float m = -INFINITY;
#pragma unroll
    for (int i = 0; i < 8; ++i) {
        v[i] = Sf[base + tid + i * 256];
        m = fmaxf(m, v[i]);
    }

    __shared__ float red[256];
    red[tid] = m;
    __syncthreads();
#pragma unroll
    for (int s = 128; s > 0; s >>= 1) {
        if (tid < s) red[tid] = fmaxf(red[tid], red[tid + s]);
        __syncthreads();
    }
    m = red[0];
    __syncthreads();

    float sum = 0.f;
#pragma unroll
    for (int i = 0; i < 8; ++i) {
        v[i] = expf(v[i] - m);
        sum += v[i];
    }
    red[tid] = sum;
    __syncthreads();
#pragma unroll
    for (int s = 128; s > 0; s >>= 1) {
        if (tid < s) red[tid] += red[tid + s];
        __syncthreads();
    }
    const float inv = 1.0f / red[0];
#pragma unroll
    for (int i = 0; i < 8; ++i)
        Sh[base + tid + i * 256] = __float2half_rn(v[i] * inv);
}

// ---------------------------------------------------------------------------
extern "C" void kernel_launch(void* const* d_in, const int* in_sizes, int n_in,
                              void* d_out, int out_size)
{
    (void)in_sizes; (void)n_in; (void)out_size;

    const float* X  = (const float*)d_in[0];
    const float* Wq = (const float*)d_in[1];
    const float* bq = (const float*)d_in[2];
    const float* Wk = (const float*)d_in[3];
    const float* bk = (const float*)d_in[4];
    const float* Wv = (const float*)d_in[5];
    const float* bv = (const float*)d_in[6];
    const float* Wh = (const float*)d_in[7];
    const float* bh = (const float*)d_in[8];
    float* out = (float*)d_out;

    __half *Xh, *Wqh, *Wql, *Wkh, *Wkl, *Wvh, *Wvl, *Whh, *Whl;
    __half *Qh, *Kh, *Kl, *Vth, *Vtl, *Sh, *Ch;
    float *Vf, *Sf;
    cudaGetSymbolAddress((void**)&Xh,  g_Xh);
    cudaGetSymbolAddress((void**)&Wqh, g_Wqh); cudaGetSymbolAddress((void**)&Wql, g_Wql);
    cudaGetSymbolAddress((void**)&Wkh, g_Wkh); cudaGetSymbolAddress((void**)&Wkl, g_Wkl);
    cudaGetSymbolAddress((void**)&Wvh, g_Wvh); cudaGetSymbolAddress((void**)&Wvl, g_Wvl);
    cudaGetSymbolAddress((void**)&Whh, g_Whh); cudaGetSymbolAddress((void**)&Whl, g_Whl);
    cudaGetSymbolAddress((void**)&Qh,  g_Qh);
    cudaGetSymbolAddress((void**)&Kh,  g_Kh);  cudaGetSymbolAddress((void**)&Kl,  g_Kl);
    cudaGetSymbolAddress((void**)&Vf,  g_Vf);
    cudaGetSymbolAddress((void**)&Vth, g_Vth); cudaGetSymbolAddress((void**)&Vtl, g_Vtl);
    cudaGetSymbolAddress((void**)&Sf,  g_Sf);
    cudaGetSymbolAddress((void**)&Sh,  g_Sh);
    cudaGetSymbolAddress((void**)&Ch,  g_Ch);

    cudaFuncSetAttribute(gemm_h<0>, cudaFuncAttributeMaxDynamicSharedMemorySize, GEMM_SMEM);
    cudaFuncSetAttribute(gemm_h<1>, cudaFuncAttributeMaxDynamicSharedMemorySize, GEMM_SMEM);
    cudaFuncSetAttribute(gemm_h<2>, cudaFuncAttributeMaxDynamicSharedMemorySize, GEMM_SMEM);

    const dim3 blk(256);
    const float scale = 1.0f / 32.0f;   // 1/sqrt(1024)

    // launch 0: X -> fp16 hi
    to_half<<<(MTOT * HID / 4 + 255) / 256, blk>>>(
        (const float4*)X, Xh, (size_t)MTOT * HID / 4);

    // launch 1: all 4 weight transposes (z-batched), fp16 hi/lo
    dim3 tgw(HID / 32, HID / 32, 4), tblk(32, 8);
    transpose_weights<<<tgw, tblk>>>(Wq, Wk, Wv, Wh,
                                     Wqh, Wql, Wkh, Wkl, Wvh, Wvl, Whh, Whl);

    // launches 2-4: projections (M=8192, N=1024, K=1024)
    dim3 gp(HID / 128, MTOT / 128, 1);
    gemm_h<1><<<gp, blk, GEMM_SMEM>>>(Xh, Wqh, Wql, bq, nullptr, Qh, nullptr,
                                      HID, HID, 0, 0, 0, 1.f);
    gemm_h<2><<<gp, blk, GEMM_SMEM>>>(Xh, Wkh, Wkl, bk, nullptr, Kh, Kl,
                                      HID, HID, 0, 0, 0, 1.f);
    gemm_h<0><<<gp, blk, GEMM_SMEM>>>(Xh, Wvh, Wvl, bv, Vf, nullptr, nullptr,
                                      HID, HID, 0, 0, 0, 1.f);

    // launch 5 (ncu target): scores = scale * Q @ K^T (batched) -> fp32
    dim3 gs(SEQ / 128, SEQ / 128, BATCH);
    gemm_h<0><<<gs, blk, GEMM_SMEM>>>(Qh, Kh, Kl, nullptr, Sf, nullptr, nullptr,
                                      SEQ, HID,
                                      (size_t)SEQ * HID, (size_t)SEQ * HID,
                                      (size_t)SEQ * SEQ, scale);

    // launch 6: V -> V^T hi/lo (per batch)
    dim3 tgv(HID / 32, SEQ / 32, BATCH);
    transpose_split<<<tgv, tblk>>>(Vf, Vth, Vtl, SEQ, HID);

    // launch 7: softmax -> fp16
    softmax_h<<<BATCH * SEQ, blk>>>(Sf, Sh);

    // launch 8: context = attn @ V (batched, K=2048) -> fp16
    dim3 gc(HID / 128, SEQ / 128, BATCH);
    gemm_h<1><<<gc, blk, GEMM_SMEM>>>(Sh, Vth, Vtl, nullptr, nullptr, Ch, nullptr,
                                      HID, SEQ,
                                      (size_t)SEQ * SEQ, (size_t)HID * SEQ,
                                      (size_t)SEQ * HID, 1.f);

    // launch 9: y = context @ Wh + bh -> d_out fp32
    dim3 go(HID / 128, MTOT / 128, 1);
    gemm_h<0><<<go, blk, GEMM_SMEM>>>(Ch, Whh, Whl, bh, out, nullptr, nullptr,
                                      HID, HID, 0, 0, 0, 1.f);
}

// round 7
// speedup vs baseline: 1.8045x; 1.1714x over previous
#include <cuda_runtime.h>
#include <cuda_fp16.h>
#include <math.h>
#include <stdint.h>

#define BATCH 4
#define SEQ   2048
#define HID   1024
#define MTOT  (BATCH * SEQ)   // 8192

// ---------------------------------------------------------------------------
// Scratch (device globals; allocation-free per harness rules)
// ---------------------------------------------------------------------------
__device__ __half g_Xh[(size_t)MTOT * HID];

__device__ __half g_Wqh[HID * HID], g_Wql[HID * HID];
__device__ __half g_Wkh[HID * HID], g_Wkl[HID * HID];
__device__ __half g_Wvh[HID * HID], g_Wvl[HID * HID];
__device__ __half g_Whh[HID * HID], g_Whl[HID * HID];

__device__ __half g_Qh[(size_t)MTOT * HID];
__device__ __half g_Kh[(size_t)MTOT * HID], g_Kl[(size_t)MTOT * HID];
__device__ float  g_Vf[(size_t)MTOT * HID];
__device__ __half g_Vth[(size_t)MTOT * HID];

__device__ float  g_Sf[(size_t)BATCH * SEQ * SEQ];
__device__ __half g_Sh[(size_t)BATCH * SEQ * SEQ];

__device__ __half g_Ch[(size_t)MTOT * HID];

// ---------------------------------------------------------------------------
// helpers
// ---------------------------------------------------------------------------
__device__ __forceinline__ uint32_t smem_u32(const void* p) {
    uint32_t a;
    asm("{ .reg .u64 t; cvta.to.shared.u64 t, %1; cvt.u32.u64 %0, t; }"
        : "=r"(a) : "l"(p));
    return a;
}

__device__ __forceinline__ void cp16(uint32_t saddr, const void* gaddr) {
    asm volatile("cp.async.cg.shared.global [%0], [%1], 16;"
                 :: "r"(saddr), "l"(gaddr));
}
__device__ __forceinline__ void cp_commit() {
    asm volatile("cp.async.commit_group;" ::: "memory");
}
template <int N>
__device__ __forceinline__ void cp_wait() {
    asm volatile("cp.async.wait_group %0;" :: "n"(N) : "memory");
}

__device__ __forceinline__ void ldsm4(uint32_t addr, uint32_t& r0, uint32_t& r1,
                                      uint32_t& r2, uint32_t& r3) {
    asm volatile("ldmatrix.sync.aligned.m8n8.x4.shared.b16 {%0,%1,%2,%3}, [%4];"
                 : "=r"(r0), "=r"(r1), "=r"(r2), "=r"(r3) : "r"(addr));
}

__device__ __forceinline__ void mma16816(float* c, const uint32_t* a,
                                         uint32_t b0, uint32_t b1) {
    asm volatile(
        "mma.sync.aligned.m16n8k16.row.col.f32.f16.f16.f32 "
        "{%0,%1,%2,%3}, {%4,%5,%6,%7}, {%8,%9}, {%0,%1,%2,%3};"
        : "+f"(c[0]), "+f"(c[1]), "+f"(c[2]), "+f"(c[3])
        : "r"(a[0]), "r"(a[1]), "r"(a[2]), "r"(a[3]), "r"(b0), "r"(b1));
}

__device__ __forceinline__ void split2h(float x, __half& h, __half& l) {
    h = __float2half_rn(x);
    l = __float2half_rn(x - __half2float(h));
}

// ldmatrix x4 source address inside a [128 rows x 64B] swizzled tile.
__device__ __forceinline__ uint32_t lds_addr(uint32_t tb, int base_row, int ks, int lane) {
    int r = base_row + ((lane >> 3) & 1) * 8 + (lane & 7);
    int c = (ks * 2 + (lane >> 4)) ^ ((r >> 1) & 3);
    return tb + (uint32_t)(r * 64 + c * 16);
}

// ---------------------------------------------------------------------------
// Emulated-fp32 NT GEMM via fp16 mma.sync:
//   C[M,N] = alpha*(A @ B^T) + bias;  A:[M,K] fp16 hi; B:[N,K] fp16 hi (+lo)
// NB = 1: single-term (B hi only, 1 MMA per step, 2 smem tiles/stage)
// NB = 2: two-term   (B hi+lo,  2 MMAs per step, 3 smem tiles/stage)
// Block 128x128, Ktile 32, 8 warps (64x32 warp tile), 2-stage cp.async ring
// (issue next-stage loads BEFORE waiting — R3/R6-proven schedule).
// OUTMODE: 0 = fp32, 1 = fp16 single, 2 = fp16 hi+lo pair.
// ---------------------------------------------------------------------------
template <int OUTMODE, int NB>
__global__ __launch_bounds__(256) void gemm_h(
    const __half* __restrict__ Ap,
    const __half* __restrict__ Bhp, const __half* __restrict__ Blp,
    const float* __restrict__ bias,
    float* __restrict__ Cf, __half* __restrict__ Ch, __half* __restrict__ Cl,
    int N, int K, size_t sA, size_t sB, size_t sC, float alpha)
{
    constexpr uint32_t STAGE = 8192u * (1 + NB);

    extern __shared__ char smem_raw[];
    const uint32_t smem = smem_u32(smem_raw);

    const int tid  = threadIdx.x;
    const int lane = tid & 31;
    const int warp = tid >> 5;
    const int wm = warp >> 2;          // 0..1  (M)
    const int wn = warp & 3;           // 0..3  (N)
    const int bn = blockIdx.x, bm = blockIdx.y, z = blockIdx.z;

    const __half* pA  = Ap  + (size_t)z * sA + (size_t)bm * 128 * K;
    const __half* pBh = Bhp + (size_t)z * sB + (size_t)bn * 128 * K;
    const __half* pBl = (NB == 2) ? Blp + (size_t)z * sB + (size_t)bn * 128 * K : nullptr;

    auto stage_load = [&](uint32_t sb, int k0) {
#pragma unroll
        for (int h = 0; h < 2; ++h) {
            const int ch  = tid + h * 256;
            const int row = ch >> 2, c = ch & 3;
            const int cs  = c ^ ((row >> 1) & 3);
            const uint32_t so = (uint32_t)(row * 64 + cs * 16);
            const size_t   go = (size_t)row * K + k0 + c * 8;
            cp16(sb +    0 + so, pA  + go);
            cp16(sb + 8192 + so, pBh + go);
            if (NB == 2) cp16(sb + 16384 + so, pBl + go);
        }
    };

    float acc[4][4][4];
#pragma unroll
    for (int i = 0; i < 4; ++i)
#pragma unroll
        for (int j = 0; j < 4; ++j)
#pragma unroll
            for (int q = 0; q < 4; ++q) acc[i][j][q] = 0.f;

    const int KT = K >> 5;

    stage_load(smem, 0);
    cp_commit();

    for (int kt = 0; kt < KT; ++kt) {
        // issue next stage FIRST (loads in flight while waiting), then wait
        if (kt + 1 < KT) {
            stage_load(smem + (uint32_t)((kt + 1) & 1) * STAGE, (kt + 1) * 32);
            cp_commit();
            cp_wait<1>();
        } else {
            cp_wait<0>();
        }
        __syncthreads();

        const uint32_t sb = smem + (uint32_t)(kt & 1) * STAGE;
#pragma unroll
        for (int ks = 0; ks < 2; ++ks) {
            uint32_t aH[4][4], bH[4][2], bL[4][2];
#pragma unroll
            for (int i = 0; i < 4; ++i)
                ldsm4(lds_addr(sb, wm * 64 + i * 16, ks, lane),
                      aH[i][0], aH[i][1], aH[i][2], aH[i][3]);
#pragma unroll
            for (int j2 = 0; j2 < 2; ++j2) {
                uint32_t r0, r1, r2, r3;
                ldsm4(lds_addr(sb + 8192, wn * 32 + j2 * 16, ks, lane), r0, r1, r2, r3);
                bH[j2 * 2 + 0][0] = r0; bH[j2 * 2 + 0][1] = r2;
                bH[j2 * 2 + 1][0] = r1; bH[j2 * 2 + 1][1] = r3;
                if (NB == 2) {
                    ldsm4(lds_addr(sb + 16384, wn * 32 + j2 * 16, ks, lane), r0, r1, r2, r3);
                    bL[j2 * 2 + 0][0] = r0; bL[j2 * 2 + 0][1] = r2;
                    bL[j2 * 2 + 1][0] = r1; bL[j2 * 2 + 1][1] = r3;
                }
            }
#pragma unroll
            for (int i = 0; i < 4; ++i)
#pragma unroll
                for (int j = 0; j < 4; ++j) {
                    mma16816(acc[i][j], aH[i], bH[j][0], bH[j][1]);
                    if (NB == 2) mma16816(acc[i][j], aH[i], bL[j][0], bL[j][1]);
                }
        }
        __syncthreads();
    }

    // epilogue
    const size_t growb = (size_t)bm * 128 + wm * 64;
    const int    gcolb = bn * 128 + wn * 32;
#pragma unroll
    for (int i = 0; i < 4; ++i) {
        const size_t r0 = growb + i * 16 + (lane >> 2);
#pragma unroll
        for (int j = 0; j < 4; ++j) {
            const int col = gcolb + j * 8 + (lane & 3) * 2;
            float b0 = 0.f, b1 = 0.f;
            if (bias) { b0 = bias[col]; b1 = bias[col + 1]; }
            const float v00 = acc[i][j][0] * alpha + b0;
            const float v01 = acc[i][j][1] * alpha + b1;
            const float v10 = acc[i][j][2] * alpha + b0;
            const float v11 = acc[i][j][3] * alpha + b1;
            const size_t o0 = (size_t)z * sC + r0 * N + col;
            const size_t o1 = o0 + (size_t)8 * N;
            if (OUTMODE == 0) {
                *reinterpret_cast<float2*>(Cf + o0) = make_float2(v00, v01);
                *reinterpret_cast<float2*>(Cf + o1) = make_float2(v10, v11);
            } else if (OUTMODE == 1) {
                *reinterpret_cast<__half2*>(Ch + o0) =
                    __halves2half2(__float2half_rn(v00), __float2half_rn(v01));
                *reinterpret_cast<__half2*>(Ch + o1) =
                    __halves2half2(__float2half_rn(v10), __float2half_rn(v11));
            } else {
                __half h0, l0, h1, l1;
                split2h(v00, h0, l0); split2h(v01, h1, l1);
                *reinterpret_cast<__half2*>(Ch + o0) = __halves2half2(h0, h1);
                *reinterpret_cast<__half2*>(Cl + o0) = __halves2half2(l0, l1);
                split2h(v10, h0, l0); split2h(v11, h1, l1);
                *reinterpret_cast<__half2*>(Ch + o1) = __halves2half2(h0, h1);
                *reinterpret_cast<__half2*>(Cl + o1) = __halves2half2(l0, l1);
            }
        }
    }
}

// ---------------------------------------------------------------------------
// fp32 -> fp16 hi-only convert (for X), vectorized by 4
// ---------------------------------------------------------------------------
__global__ __launch_bounds__(256) void to_half(
    const float4* __restrict__ in, __half* __restrict__ h, size_t n4)
{
    size_t i = (size_t)blockIdx.x * blockDim.x + threadIdx.x;
    if (i >= n4) return;
    float4 v = in[i];
    __align__(8) __half hb[4];
    hb[0] = __float2half_rn(v.x);
    hb[1] = __float2half_rn(v.y);
    hb[2] = __float2half_rn(v.z);
    hb[3] = __float2half_rn(v.w);
    reinterpret_cast<uint2*>(h)[i] = *reinterpret_cast<uint2*>(hb);
}

// ---------------------------------------------------------------------------
// Transpose (hi only): in [R,C] fp32 -> fp16 [C,R] (z-batched). For V.
// ---------------------------------------------------------------------------
__global__ __launch_bounds__(256) void transpose_hi(
    const float* __restrict__ in, __half* __restrict__ hT, int R, int C)
{
    __shared__ float t[32][33];
    const size_t zoff = (size_t)blockIdx.z * R * C;
    const int r0 = blockIdx.y * 32, c0 = blockIdx.x * 32;
    const int tx = threadIdx.x, ty = threadIdx.y;   // (32, 8)
#pragma unroll
    for (int j = 0; j < 4; ++j)
        t[ty + 8 * j][tx] = in[zoff + (size_t)(r0 + ty + 8 * j) * C + c0 + tx];
    __syncthreads();
#pragma unroll
    for (int j = 0; j < 4; ++j) {
        size_t o = zoff + (size_t)(c0 + ty + 8 * j) * R + r0 + tx;
        hT[o] = __float2half_rn(t[tx][ty + 8 * j]);
    }
}

// ---------------------------------------------------------------------------
// All 4 weight transposes in ONE launch (z selects the weight).
// Wh (z=3) needs hi only; others write hi+lo.
// ---------------------------------------------------------------------------
__global__ __launch_bounds__(256) void transpose_weights(
    const float* __restrict__ W0, const float* __restrict__ W1,
    const float* __restrict__ W2, const float* __restrict__ W3,
    __half* __restrict__ H0, __half* __restrict__ L0,
    __half* __restrict__ H1, __half* __restrict__ L1,
    __half* __restrict__ H2, __half* __restrict__ L2,
    __half* __restrict__ H3)
{
    __shared__ float t[32][33];
    const int zi = blockIdx.z;
    const float* in = (zi == 0) ? W0 : (zi == 1) ? W1 : (zi == 2) ? W2 : W3;
    __half* hT = (zi == 0) ? H0 : (zi == 1) ? H1 : (zi == 2) ? H2 : H3;
    __half* lT = (zi == 0) ? L0 : (zi == 1) ? L1 : (zi == 2) ? L2 : nullptr;

    const int r0 = blockIdx.y * 32, c0 = blockIdx.x * 32;
    const int tx = threadIdx.x, ty = threadIdx.y;   // (32, 8)
#pragma unroll
    for (int j = 0; j < 4; ++j)
        t[ty + 8 * j][tx] = in[(size_t)(r0 + ty + 8 * j) * HID + c0 + tx];
    __syncthreads();
#pragma unroll
    for (int j = 0; j < 4; ++j) {
        float v = t[tx][ty + 8 * j];
        __half h, l;
        split2h(v, h, l);
        size_t o = (size_t)(c0 + ty + 8 * j) * HID + r0 + tx;
        hT[o] = h;
        if (lT) lT[o] = l;
    }
}

// ---------------------------------------------------------------------------
// Row softmax over 2048 cols, fp32 in, fp16 out.
// ---------------------------------------------------------------------------
__global__ __launch_bounds__(256) void softmax_h(
    const float* __restrict__ Sf, __half* __restrict__ Sh)
{
    const size_t base = (size_t)blockIdx.x * SEQ;
    const int tid = threadIdx.x;

    float v[8];
    float m = -INFINITY;
#pragma unroll
    for (int i = 0; i < 8; ++i) {
        v[i] = Sf[base + tid + i * 256];
        m = fmaxf(m, v[i]);
    }

    __shared__ float red[256];
    red[tid] = m;
    __syncthreads();
#pragma unroll
    for (int s = 128; s > 0; s >>= 1) {
        if (tid < s) red[tid] = fmaxf(red[tid], red[tid + s]);
        __syncthreads();
    }
    m = red[0];
    __syncthreads();

    float sum = 0.f;
#pragma unroll
    for (int i = 0; i < 8; ++i) {
        v[i] = expf(v[i] - m);
        sum += v[i];
    }
    red[tid] = sum;
    __syncthreads();
#pragma unroll
    for (int s = 128; s > 0; s >>= 1) {
        if (tid < s) red[tid] += red[tid + s];
        __syncthreads();
    }
    const float inv = 1.0f / red[0];
#pragma unroll
    for (int i = 0; i < 8; ++i)
        Sh[base + tid + i * 256] = __float2half_rn(v[i] * inv);
}

// ---------------------------------------------------------------------------
extern "C" void kernel_launch(void* const* d_in, const int* in_sizes, int n_in,
                              void* d_out, int out_size)
{
    (void)in_sizes; (void)n_in; (void)out_size;

    const float* X  = (const float*)d_in[0];
    const float* Wq = (const float*)d_in[1];
    const float* bq = (const float*)d_in[2];
    const float* Wk = (const float*)d_in[3];
    const float* bk = (const float*)d_in[4];
    const float* Wv = (const float*)d_in[5];
    const float* bv = (const float*)d_in[6];
    const float* Wh = (const float*)d_in[7];
    const float* bh = (const float*)d_in[8];
    float* out = (float*)d_out;

    __half *Xh, *Wqh, *Wql, *Wkh, *Wkl, *Wvh, *Wvl, *Whh;
    __half *Qh, *Kh, *Kl, *Vth, *Sh, *Ch;
    float *Vf, *Sf;
    cudaGetSymbolAddress((void**)&Xh,  g_Xh);
    cudaGetSymbolAddress((void**)&Wqh, g_Wqh); cudaGetSymbolAddress((void**)&Wql, g_Wql);
    cudaGetSymbolAddress((void**)&Wkh, g_Wkh); cudaGetSymbolAddress((void**)&Wkl, g_Wkl);
    cudaGetSymbolAddress((void**)&Wvh, g_Wvh); cudaGetSymbolAddress((void**)&Wvl, g_Wvl);
    cudaGetSymbolAddress((void**)&Whh, g_Whh);
    cudaGetSymbolAddress((void**)&Qh,  g_Qh);
    cudaGetSymbolAddress((void**)&Kh,  g_Kh);  cudaGetSymbolAddress((void**)&Kl,  g_Kl);
    cudaGetSymbolAddress((void**)&Vf,  g_Vf);
    cudaGetSymbolAddress((void**)&Vth, g_Vth);
    cudaGetSymbolAddress((void**)&Sf,  g_Sf);
    cudaGetSymbolAddress((void**)&Sh,  g_Sh);
    cudaGetSymbolAddress((void**)&Ch,  g_Ch);

    const int SMEM2 = 49152;   // NB=2: 2 stages * 3 tiles
    const int SMEM1 = 32768;   // NB=1: 2 stages * 2 tiles
    cudaFuncSetAttribute(gemm_h<0,2>, cudaFuncAttributeMaxDynamicSharedMemorySize, SMEM2);
    cudaFuncSetAttribute(gemm_h<1,2>, cudaFuncAttributeMaxDynamicSharedMemorySize, SMEM2);
    cudaFuncSetAttribute(gemm_h<2,2>, cudaFuncAttributeMaxDynamicSharedMemorySize, SMEM2);
    cudaFuncSetAttribute(gemm_h<0,1>, cudaFuncAttributeMaxDynamicSharedMemorySize, SMEM1);
    cudaFuncSetAttribute(gemm_h<1,1>, cudaFuncAttributeMaxDynamicSharedMemorySize, SMEM1);

    const dim3 blk(256);
    const float scale = 1.0f / 32.0f;   // 1/sqrt(1024)

    // launch 0: X -> fp16 hi
    to_half<<<(MTOT * HID / 4 + 255) / 256, blk>>>(
        (const float4*)X, Xh, (size_t)MTOT * HID / 4);

    // launch 1: weight transposes (z-batched), fp16 hi/lo (Wh: hi only)
    dim3 tgw(HID / 32, HID / 32, 4), tblk(32, 8);
    transpose_weights<<<tgw, tblk>>>(Wq, Wk, Wv, Wh,
                                     Wqh, Wql, Wkh, Wkl, Wvh, Wvl, Whh);

    // launches 2-4: projections (2-term, M=8192, N=1024, K=1024)
    dim3 gp(HID / 128, MTOT / 128, 1);
    gemm_h<1,2><<<gp, blk, SMEM2>>>(Xh, Wqh, Wql, bq, nullptr, Qh, nullptr,
                                    HID, HID, 0, 0, 0, 1.f);
    gemm_h<2,2><<<gp, blk, SMEM2>>>(Xh, Wkh, Wkl, bk, nullptr, Kh, Kl,
                                    HID, HID, 0, 0, 0, 1.f);
    gemm_h<0,2><<<gp, blk, SMEM2>>>(Xh, Wvh, Wvl, bv, Vf, nullptr, nullptr,
                                    HID, HID, 0, 0, 0, 1.f);

    // launch 5 (ncu target): scores = scale * Q @ K^T (2-term, batched) -> fp32
    dim3 gs(SEQ / 128, SEQ / 128, BATCH);
    gemm_h<0,2><<<gs, blk, SMEM2>>>(Qh, Kh, Kl, nullptr, Sf, nullptr, nullptr,
                                    SEQ, HID,
                                    (size_t)SEQ * HID, (size_t)SEQ * HID,
                                    (size_t)SEQ * SEQ, scale);

    // launch 6: V -> V^T hi (per batch)
    dim3 tgv(HID / 32, SEQ / 32, BATCH);
    transpose_hi<<<tgv, tblk>>>(Vf, Vth, SEQ, HID);

    // launch 7: softmax -> fp16
    softmax_h<<<BATCH * SEQ, blk>>>(Sf, Sh);

    // launch 8: context = attn @ V (1-term, batched, K=2048) -> fp16
    dim3 gc(HID / 128, SEQ / 128, BATCH);
    gemm_h<1,1><<<gc, blk, SMEM1>>>(Sh, Vth, nullptr, nullptr, nullptr, Ch, nullptr,
                                    HID, SEQ,
                                    (size_t)SEQ * SEQ, (size_t)HID * SEQ,
                                    (size_t)SEQ * HID, 1.f);

    // launch 9: y = context @ Wh + bh (1-term) -> d_out fp32
    dim3 go(HID / 128, MTOT / 128, 1);
    gemm_h<0,1><<<go, blk, SMEM1>>>(Ch, Whh, nullptr, bh, out, nullptr, nullptr,
                                    HID, HID, 0, 0, 0, 1.f);
}

// round 8
// speedup vs baseline: 2.1334x; 1.1823x over previous
#include <cuda_runtime.h>
#include <cuda_fp16.h>
#include <math.h>
#include <stdint.h>

#define BATCH 4
#define SEQ   2048
#define HID   1024
#define MTOT  (BATCH * SEQ)   // 8192

// ---------------------------------------------------------------------------
// Scratch (device globals; allocation-free per harness rules)
// ---------------------------------------------------------------------------
__device__ __half g_Xh[(size_t)MTOT * HID];

__device__ __half g_Wqh[HID * HID], g_Wql[HID * HID];
__device__ __half g_Wkh[HID * HID], g_Wkl[HID * HID];
__device__ __half g_Wvh[HID * HID];
__device__ __half g_Whh[HID * HID];

__device__ __half g_Qh[(size_t)MTOT * HID];
__device__ __half g_Kh[(size_t)MTOT * HID];
__device__ float  g_Vf[(size_t)MTOT * HID];
__device__ __half g_Vth[(size_t)MTOT * HID];

__device__ float  g_Sf[(size_t)BATCH * SEQ * SEQ];
__device__ __half g_Sh[(size_t)BATCH * SEQ * SEQ];

__device__ __half g_Ch[(size_t)MTOT * HID];

// ---------------------------------------------------------------------------
// helpers
// ---------------------------------------------------------------------------
__device__ __forceinline__ uint32_t smem_u32(const void* p) {
    uint32_t a;
    asm("{ .reg .u64 t; cvta.to.shared.u64 t, %1; cvt.u32.u64 %0, t; }"
        : "=r"(a) : "l"(p));
    return a;
}

__device__ __forceinline__ void cp16(uint32_t saddr, const void* gaddr) {
    asm volatile("cp.async.cg.shared.global [%0], [%1], 16;"
                 :: "r"(saddr), "l"(gaddr));
}
__device__ __forceinline__ void cp_commit() {
    asm volatile("cp.async.commit_group;" ::: "memory");
}
template <int N>
__device__ __forceinline__ void cp_wait() {
    asm volatile("cp.async.wait_group %0;" :: "n"(N) : "memory");
}

__device__ __forceinline__ void ldsm4(uint32_t addr, uint32_t& r0, uint32_t& r1,
                                      uint32_t& r2, uint32_t& r3) {
    asm volatile("ldmatrix.sync.aligned.m8n8.x4.shared.b16 {%0,%1,%2,%3}, [%4];"
                 : "=r"(r0), "=r"(r1), "=r"(r2), "=r"(r3) : "r"(addr));
}

__device__ __forceinline__ void mma16816(float* c, const uint32_t* a,
                                         uint32_t b0, uint32_t b1) {
    asm volatile(
        "mma.sync.aligned.m16n8k16.row.col.f32.f16.f16.f32 "
        "{%0,%1,%2,%3}, {%4,%5,%6,%7}, {%8,%9}, {%0,%1,%2,%3};"
        : "+f"(c[0]), "+f"(c[1]), "+f"(c[2]), "+f"(c[3])
        : "r"(a[0]), "r"(a[1]), "r"(a[2]), "r"(a[3]), "r"(b0), "r"(b1));
}

__device__ __forceinline__ void split2h(float x, __half& h, __half& l) {
    h = __float2half_rn(x);
    l = __float2half_rn(x - __half2float(h));
}

// ldmatrix x4 source address inside a [128 rows x 64B] swizzled tile.
__device__ __forceinline__ uint32_t lds_addr(uint32_t tb, int base_row, int ks, int lane) {
    int r = base_row + ((lane >> 3) & 1) * 8 + (lane & 7);
    int c = (ks * 2 + (lane >> 4)) ^ ((r >> 1) & 3);
    return tb + (uint32_t)(r * 64 + c * 16);
}

// ---------------------------------------------------------------------------
// Emulated-fp32 NT GEMM via fp16 mma.sync:
//   C[M,N] = alpha*(A @ B^T) + bias;  A:[M,K] fp16 hi; B:[N,K] fp16 hi (+lo)
// NB = 1: single-term (B hi only, 1 MMA per step, 2 smem tiles/stage)
// NB = 2: two-term   (B hi+lo,  2 MMAs per step, 3 smem tiles/stage)
// Block 128x128, Ktile 32, 8 warps (64x32 warp tile), 2-stage cp.async ring
// (issue next-stage loads BEFORE waiting — proven schedule).
// OUTMODE: 0 = fp32, 1 = fp16 single.
// ---------------------------------------------------------------------------
template <int OUTMODE, int NB>
__global__ __launch_bounds__(256) void gemm_h(
    const __half* __restrict__ Ap,
    const __half* __restrict__ Bhp, const __half* __restrict__ Blp,
    const float* __restrict__ bias,
    float* __restrict__ Cf, __half* __restrict__ Ch,
    int N, int K, size_t sA, size_t sB, size_t sC, float alpha)
{
    constexpr uint32_t STAGE = 8192u * (1 + NB);

    extern __shared__ char smem_raw[];
    const uint32_t smem = smem_u32(smem_raw);

    const int tid  = threadIdx.x;
    const int lane = tid & 31;
    const int warp = tid >> 5;
    const int wm = warp >> 2;          // 0..1  (M)
    const int wn = warp & 3;           // 0..3  (N)
    const int bn = blockIdx.x, bm = blockIdx.y, z = blockIdx.z;

    const __half* pA  = Ap  + (size_t)z * sA + (size_t)bm * 128 * K;
    const __half* pBh = Bhp + (size_t)z * sB + (size_t)bn * 128 * K;
    const __half* pBl = (NB == 2) ? Blp + (size_t)z * sB + (size_t)bn * 128 * K : nullptr;

    auto stage_load = [&](uint32_t sb, int k0) {
#pragma unroll
        for (int h = 0; h < 2; ++h) {
            const int ch  = tid + h * 256;
            const int row = ch >> 2, c = ch & 3;
            const int cs  = c ^ ((row >> 1) & 3);
            const uint32_t so = (uint32_t)(row * 64 + cs * 16);
            const size_t   go = (size_t)row * K + k0 + c * 8;
            cp16(sb +    0 + so, pA  + go);
            cp16(sb + 8192 + so, pBh + go);
            if (NB == 2) cp16(sb + 16384 + so, pBl + go);
        }
    };

    float acc[4][4][4];
#pragma unroll
    for (int i = 0; i < 4; ++i)
#pragma unroll
        for (int j = 0; j < 4; ++j)
#pragma unroll
            for (int q = 0; q < 4; ++q) acc[i][j][q] = 0.f;

    const int KT = K >> 5;

    stage_load(smem, 0);
    cp_commit();

    for (int kt = 0; kt < KT; ++kt) {
        // issue next stage FIRST (loads in flight while waiting), then wait
        if (kt + 1 < KT) {
            stage_load(smem + (uint32_t)((kt + 1) & 1) * STAGE, (kt + 1) * 32);
            cp_commit();
            cp_wait<1>();
        } else {
            cp_wait<0>();
        }
        __syncthreads();

        const uint32_t sb = smem + (uint32_t)(kt & 1) * STAGE;
#pragma unroll
        for (int ks = 0; ks < 2; ++ks) {
            uint32_t aH[4][4], bH[4][2], bL[4][2];
#pragma unroll
            for (int i = 0; i < 4; ++i)
                ldsm4(lds_addr(sb, wm * 64 + i * 16, ks, lane),
                      aH[i][0], aH[i][1], aH[i][2], aH[i][3]);
#pragma unroll
            for (int j2 = 0; j2 < 2; ++j2) {
                uint32_t r0, r1, r2, r3;
                ldsm4(lds_addr(sb + 8192, wn * 32 + j2 * 16, ks, lane), r0, r1, r2, r3);
                bH[j2 * 2 + 0][0] = r0; bH[j2 * 2 + 0][1] = r2;
                bH[j2 * 2 + 1][0] = r1; bH[j2 * 2 + 1][1] = r3;
                if (NB == 2) {
                    ldsm4(lds_addr(sb + 16384, wn * 32 + j2 * 16, ks, lane), r0, r1, r2, r3);
                    bL[j2 * 2 + 0][0] = r0; bL[j2 * 2 + 0][1] = r2;
                    bL[j2 * 2 + 1][0] = r1; bL[j2 * 2 + 1][1] = r3;
                }
            }
#pragma unroll
            for (int i = 0; i < 4; ++i)
#pragma unroll
                for (int j = 0; j < 4; ++j) {
                    mma16816(acc[i][j], aH[i], bH[j][0], bH[j][1]);
                    if (NB == 2) mma16816(acc[i][j], aH[i], bL[j][0], bL[j][1]);
                }
        }
        __syncthreads();
    }

    // epilogue
    const size_t growb = (size_t)bm * 128 + wm * 64;
    const int    gcolb = bn * 128 + wn * 32;
#pragma unroll
    for (int i = 0; i < 4; ++i) {
        const size_t r0 = growb + i * 16 + (lane >> 2);
#pragma unroll
        for (int j = 0; j < 4; ++j) {
            const int col = gcolb + j * 8 + (lane & 3) * 2;
            float b0 = 0.f, b1 = 0.f;
            if (bias) { b0 = bias[col]; b1 = bias[col + 1]; }
            const float v00 = acc[i][j][0] * alpha + b0;
            const float v01 = acc[i][j][1] * alpha + b1;
            const float v10 = acc[i][j][2] * alpha + b0;
            const float v11 = acc[i][j][3] * alpha + b1;
            const size_t o0 = (size_t)z * sC + r0 * N + col;
            const size_t o1 = o0 + (size_t)8 * N;
            if (OUTMODE == 0) {
                *reinterpret_cast<float2*>(Cf + o0) = make_float2(v00, v01);
                *reinterpret_cast<float2*>(Cf + o1) = make_float2(v10, v11);
            } else {
                *reinterpret_cast<__half2*>(Ch + o0) =
                    __halves2half2(__float2half_rn(v00), __float2half_rn(v01));
                *reinterpret_cast<__half2*>(Ch + o1) =
                    __halves2half2(__float2half_rn(v10), __float2half_rn(v11));
            }
        }
    }
}

// ---------------------------------------------------------------------------
// fp32 -> fp16 hi-only convert (for X), vectorized by 4
// ---------------------------------------------------------------------------
__global__ __launch_bounds__(256) void to_half(
    const float4* __restrict__ in, __half* __restrict__ h, size_t n4)
{
    size_t i = (size_t)blockIdx.x * blockDim.x + threadIdx.x;
    if (i >= n4) return;
    float4 v = in[i];
    __align__(8) __half hb[4];
    hb[0] = __float2half_rn(v.x);
    hb[1] = __float2half_rn(v.y);
    hb[2] = __float2half_rn(v.z);
    hb[3] = __float2half_rn(v.w);
    reinterpret_cast<uint2*>(h)[i] = *reinterpret_cast<uint2*>(hb);
}

// ---------------------------------------------------------------------------
// Transpose (hi only): in [R,C] fp32 -> fp16 [C,R] (z-batched). For V.
// ---------------------------------------------------------------------------
__global__ __launch_bounds__(256) void transpose_hi(
    const float* __restrict__ in, __half* __restrict__ hT, int R, int C)
{
    __shared__ float t[32][33];
    const size_t zoff = (size_t)blockIdx.z * R * C;
    const int r0 = blockIdx.y * 32, c0 = blockIdx.x * 32;
    const int tx = threadIdx.x, ty = threadIdx.y;   // (32, 8)
#pragma unroll
    for (int j = 0; j < 4; ++j)
        t[ty + 8 * j][tx] = in[zoff + (size_t)(r0 + ty + 8 * j) * C + c0 + tx];
    __syncthreads();
#pragma unroll
    for (int j = 0; j < 4; ++j) {
        size_t o = zoff + (size_t)(c0 + ty + 8 * j) * R + r0 + tx;
        hT[o] = __float2half_rn(t[tx][ty + 8 * j]);
    }
}

// ---------------------------------------------------------------------------
// All 4 weight transposes in ONE launch (z selects the weight).
// Wq (z=0) and Wk (z=1) write hi+lo; Wv (z=2) and Wh (z=3) hi only.
// ---------------------------------------------------------------------------
__global__ __launch_bounds__(256) void transpose_weights(
    const float* __restrict__ W0, const float* __restrict__ W1,
    const float* __restrict__ W2, const float* __restrict__ W3,
    __half* __restrict__ H0, __half* __restrict__ L0,
    __half* __restrict__ H1, __half* __restrict__ L1,
    __half* __restrict__ H2, __half* __restrict__ H3)
{
    __shared__ float t[32][33];
    const int zi = blockIdx.z;
    const float* in = (zi == 0) ? W0 : (zi == 1) ? W1 : (zi == 2) ? W2 : W3;
    __half* hT = (zi == 0) ? H0 : (zi == 1) ? H1 : (zi == 2) ? H2 : H3;
    __half* lT = (zi == 0) ? L0 : (zi == 1) ? L1 : nullptr;

    const int r0 = blockIdx.y * 32, c0 = blockIdx.x * 32;
    const int tx = threadIdx.x, ty = threadIdx.y;   // (32, 8)
#pragma unroll
    for (int j = 0; j < 4; ++j)
        t[ty + 8 * j][tx] = in[(size_t)(r0 + ty + 8 * j) * HID + c0 + tx];
    __syncthreads();
#pragma unroll
    for (int j = 0; j < 4; ++j) {
        float v = t[tx][ty + 8 * j];
        __half h, l;
        split2h(v, h, l);
        size_t o = (size_t)(c0 + ty + 8 * j) * HID + r0 + tx;
        hT[o] = h;
        if (lT) lT[o] = l;
    }
}

// ---------------------------------------------------------------------------
// Row softmax over 2048 cols, fp32 in, fp16 out.
// ---------------------------------------------------------------------------
__global__ __launch_bounds__(256) void softmax_h(
    const float* __restrict__ Sf, __half* __restrict__ Sh)
{
    const size_t base = (size_t)blockIdx.x * SEQ;
    const int tid = threadIdx.x;

    float v[8];
    float m = -INFINITY;
#pragma unroll
    for (int i = 0; i < 8; ++i) {
        v[i] = Sf[base + tid + i * 256];
        m = fmaxf(m, v[i]);
    }

    __shared__ float red[256];
    red[tid] = m;
    __syncthreads();
#pragma unroll
    for (int s = 128; s > 0; s >>= 1) {
        if (tid < s) red[tid] = fmaxf(red[tid], red[tid + s]);
        __syncthreads();
    }
    m = red[0];
    __syncthreads();

    float sum = 0.f;
#pragma unroll
    for (int i = 0; i < 8; ++i) {
        v[i] = expf(v[i] - m);
        sum += v[i];
    }
    red[tid] = sum;
    __syncthreads();
#pragma unroll
    for (int s = 128; s > 0; s >>= 1) {
        if (tid < s) red[tid] += red[tid + s];
        __syncthreads();
    }
    const float inv = 1.0f / red[0];
#pragma unroll
    for (int i = 0; i < 8; ++i)
        Sh[base + tid + i * 256] = __float2half_rn(v[i] * inv);
}

// ---------------------------------------------------------------------------
extern "C" void kernel_launch(void* const* d_in, const int* in_sizes, int n_in,
                              void* d_out, int out_size)
{
    (void)in_sizes; (void)n_in; (void)out_size;

    const float* X  = (const float*)d_in[0];
    const float* Wq = (const float*)d_in[1];
    const float* bq = (const float*)d_in[2];
    const float* Wk = (const float*)d_in[3];
    const float* bk = (const float*)d_in[4];
    const float* Wv = (const float*)d_in[5];
    const float* bv = (const float*)d_in[6];
    const float* Wh = (const float*)d_in[7];
    const float* bh = (const float*)d_in[8];
    float* out = (float*)d_out;

    __half *Xh, *Wqh, *Wql, *Wkh, *Wkl, *Wvh, *Whh;
    __half *Qh, *Kh, *Vth, *Sh, *Ch;
    float *Vf, *Sf;
    cudaGetSymbolAddress((void**)&Xh,  g_Xh);
    cudaGetSymbolAddress((void**)&Wqh, g_Wqh); cudaGetSymbolAddress((void**)&Wql, g_Wql);
    cudaGetSymbolAddress((void**)&Wkh, g_Wkh); cudaGetSymbolAddress((void**)&Wkl, g_Wkl);
    cudaGetSymbolAddress((void**)&Wvh, g_Wvh);
    cudaGetSymbolAddress((void**)&Whh, g_Whh);
    cudaGetSymbolAddress((void**)&Qh,  g_Qh);
    cudaGetSymbolAddress((void**)&Kh,  g_Kh);
    cudaGetSymbolAddress((void**)&Vf,  g_Vf);
    cudaGetSymbolAddress((void**)&Vth, g_Vth);
    cudaGetSymbolAddress((void**)&Sf,  g_Sf);
    cudaGetSymbolAddress((void**)&Sh,  g_Sh);
    cudaGetSymbolAddress((void**)&Ch,  g_Ch);

    const int SMEM2 = 49152;   // NB=2: 2 stages * 3 tiles
    const int SMEM1 = 32768;   // NB=1: 2 stages * 2 tiles
    cudaFuncSetAttribute(gemm_h<0,2>, cudaFuncAttributeMaxDynamicSharedMemorySize, SMEM2);
    cudaFuncSetAttribute(gemm_h<1,2>, cudaFuncAttributeMaxDynamicSharedMemorySize, SMEM2);
    cudaFuncSetAttribute(gemm_h<0,1>, cudaFuncAttributeMaxDynamicSharedMemorySize, SMEM1);
    cudaFuncSetAttribute(gemm_h<1,1>, cudaFuncAttributeMaxDynamicSharedMemorySize, SMEM1);

    const dim3 blk(256);
    const float scale = 1.0f / 32.0f;   // 1/sqrt(1024)

    // launch 0: X -> fp16 hi
    to_half<<<(MTOT * HID / 4 + 255) / 256, blk>>>(
        (const float4*)X, Xh, (size_t)MTOT * HID / 4);

    // launch 1: weight transposes (z-batched); Wq/Wk hi+lo, Wv/Wh hi only
    dim3 tgw(HID / 32, HID / 32, 4), tblk(32, 8);
    transpose_weights<<<tgw, tblk>>>(Wq, Wk, Wv, Wh,
                                     Wqh, Wql, Wkh, Wkl, Wvh, Whh);

    // launches 2-4: projections (M=8192, N=1024, K=1024)
    dim3 gp(HID / 128, MTOT / 128, 1);
    gemm_h<1,2><<<gp, blk, SMEM2>>>(Xh, Wqh, Wql, bq, nullptr, Qh,
                                    HID, HID, 0, 0, 0, 1.f);   // Q: 2-term
    gemm_h<1,2><<<gp, blk, SMEM2>>>(Xh, Wkh, Wkl, bk, nullptr, Kh,
                                    HID, HID, 0, 0, 0, 1.f);   // K: 2-term, hi out
    gemm_h<0,1><<<gp, blk, SMEM1>>>(Xh, Wvh, nullptr, bv, Vf, nullptr,
                                    HID, HID, 0, 0, 0, 1.f);   // V: 1-term

    // launch 5 (ncu target): scores = scale * Q @ K^T (1-term, batched) -> fp32
    dim3 gs(SEQ / 128, SEQ / 128, BATCH);
    gemm_h<0,1><<<gs, blk, SMEM1>>>(Qh, Kh, nullptr, nullptr, Sf, nullptr,
                                    SEQ, HID,
                                    (size_t)SEQ * HID, (size_t)SEQ * HID,
                                    (size_t)SEQ * SEQ, scale);

    // launch 6: V -> V^T hi (per batch)
    dim3 tgv(HID / 32, SEQ / 32, BATCH);
    transpose_hi<<<tgv, tblk>>>(Vf, Vth, SEQ, HID);

    // launch 7: softmax -> fp16
    softmax_h<<<BATCH * SEQ, blk>>>(Sf, Sh);

    // launch 8: context = attn @ V (1-term, batched, K=2048) -> fp16
    dim3 gc(HID / 128, SEQ / 128, BATCH);
    gemm_h<1,1><<<gc, blk, SMEM1>>>(Sh, Vth, nullptr, nullptr, nullptr, Ch,
                                    HID, SEQ,
                                    (size_t)SEQ * SEQ, (size_t)HID * SEQ,
                                    (size_t)SEQ * HID, 1.f);

    // launch 9: y = context @ Wh + bh (1-term) -> d_out fp32
    dim3 go(HID / 128, MTOT / 128, 1);
    gemm_h<0,1><<<go, blk, SMEM1>>>(Ch, Whh, nullptr, bh, out, nullptr,
                                    HID, HID, 0, 0, 0, 1.f);
}

// round 10
// speedup vs baseline: 2.5322x; 1.1869x over previous
#include <cuda_runtime.h>
#include <cuda_fp16.h>
#include <math.h>
#include <stdint.h>

#define BATCH 4
#define SEQ   2048
#define HID   1024
#define MTOT  (BATCH * SEQ)   // 8192

// ---------------------------------------------------------------------------
// Scratch (device globals; allocation-free per harness rules)
// ---------------------------------------------------------------------------
__device__ __half g_Xh[(size_t)MTOT * HID];

__device__ __half g_Wqh[HID * HID];
__device__ __half g_Wkh[HID * HID];
__device__ __half g_Wvh[HID * HID];
__device__ __half g_Whh[HID * HID];

__device__ __half g_Qh[(size_t)MTOT * HID];
__device__ __half g_Kh[(size_t)MTOT * HID];
__device__ __half g_Vth[(size_t)MTOT * HID];   // per-batch [HID, SEQ]

__device__ float  g_Sf[(size_t)BATCH * SEQ * SEQ];
__device__ __half g_Sh[(size_t)BATCH * SEQ * SEQ];

__device__ __half g_Ch[(size_t)MTOT * HID];

// ---------------------------------------------------------------------------
// helpers
// ---------------------------------------------------------------------------
__device__ __forceinline__ uint32_t smem_u32(const void* p) {
    uint32_t a;
    asm("{ .reg .u64 t; cvta.to.shared.u64 t, %1; cvt.u32.u64 %0, t; }"
        : "=r"(a) : "l"(p));
    return a;
}

__device__ __forceinline__ void cp16(uint32_t saddr, const void* gaddr) {
    asm volatile("cp.async.cg.shared.global [%0], [%1], 16;"
                 :: "r"(saddr), "l"(gaddr));
}
__device__ __forceinline__ void cp_commit() {
    asm volatile("cp.async.commit_group;" ::: "memory");
}
template <int N>
__device__ __forceinline__ void cp_wait() {
    asm volatile("cp.async.wait_group %0;" :: "n"(N) : "memory");
}

__device__ __forceinline__ void ldsm4(uint32_t addr, uint32_t& r0, uint32_t& r1,
                                      uint32_t& r2, uint32_t& r3) {
    asm volatile("ldmatrix.sync.aligned.m8n8.x4.shared.b16 {%0,%1,%2,%3}, [%4];"
                 : "=r"(r0), "=r"(r1), "=r"(r2), "=r"(r3) : "r"(addr));
}

__device__ __forceinline__ void mma16816(float* c, const uint32_t* a,
                                         uint32_t b0, uint32_t b1) {
    asm volatile(
        "mma.sync.aligned.m16n8k16.row.col.f32.f16.f16.f32 "
        "{%0,%1,%2,%3}, {%4,%5,%6,%7}, {%8,%9}, {%0,%1,%2,%3};"
        : "+f"(c[0]), "+f"(c[1]), "+f"(c[2]), "+f"(c[3])
        : "r"(a[0]), "r"(a[1]), "r"(a[2]), "r"(a[3]), "r"(b0), "r"(b1));
}

// ldmatrix x4 source address inside a [128 rows x 64B] swizzled tile.
__device__ __forceinline__ uint32_t lds_addr(uint32_t tb, int base_row, int ks, int lane) {
    int r = base_row + ((lane >> 3) & 1) * 8 + (lane & 7);
    int c = (ks * 2 + (lane >> 4)) ^ ((r >> 1) & 3);
    return tb + (uint32_t)(r * 64 + c * 16);
}

// ---------------------------------------------------------------------------
// fp16 NT GEMM (fp32 accum): C[M,N] = alpha*(A @ B^T) + bias
//   A:[M,K] fp16 K-major; B:[N,K] fp16 K-major
// Block 128x128, Ktile 32, 8 warps (64x32 warp tile), 2-stage cp.async ring.
// OUTMODE: 0 = fp32, 1 = fp16.  BIAS: 0 = none, 1 = per-col, 2 = per-row.
// ---------------------------------------------------------------------------
#define STAGE_BYTES 16384u
#define GEMM_SMEM   32768   // 2 stages * 2 tiles * 8KB

template <int OUTMODE, int BIAS>
__global__ __launch_bounds__(256) void gemm_h(
    const __half* __restrict__ Ap, const __half* __restrict__ Bp,
    const float* __restrict__ bias,
    float* __restrict__ Cf, __half* __restrict__ Ch,
    int N, int K, size_t sA, size_t sB, size_t sC, float alpha)
{
    extern __shared__ char smem_raw[];
    const uint32_t smem = smem_u32(smem_raw);

    const int tid  = threadIdx.x;
    const int lane = tid & 31;
    const int warp = tid >> 5;
    const int wm = warp >> 2;          // 0..1  (M)
    const int wn = warp & 3;           // 0..3  (N)
    const int bn = blockIdx.x, bm = blockIdx.y, z = blockIdx.z;

    const __half* pA = Ap + (size_t)z * sA + (size_t)bm * 128 * K;
    const __half* pB = Bp + (size_t)z * sB + (size_t)bn * 128 * K;

    auto stage_load = [&](uint32_t sb, int k0) {
#pragma unroll
        for (int h = 0; h < 2; ++h) {
            const int ch  = tid + h * 256;
            const int row = ch >> 2, c = ch & 3;
            const int cs  = c ^ ((row >> 1) & 3);
            const uint32_t so = (uint32_t)(row * 64 + cs * 16);
            const size_t   go = (size_t)row * K + k0 + c * 8;
            cp16(sb +    0 + so, pA + go);
            cp16(sb + 8192 + so, pB + go);
        }
    };

    float acc[4][4][4];
#pragma unroll
    for (int i = 0; i < 4; ++i)
#pragma unroll
        for (int j = 0; j < 4; ++j)
#pragma unroll
            for (int q = 0; q < 4; ++q) acc[i][j][q] = 0.f;

    const int KT = K >> 5;

    stage_load(smem, 0);
    cp_commit();

    for (int kt = 0; kt < KT; ++kt) {
        // issue next stage FIRST (loads in flight while waiting), then wait
        if (kt + 1 < KT) {
            stage_load(smem + (uint32_t)((kt + 1) & 1) * STAGE_BYTES, (kt + 1) * 32);
            cp_commit();
            cp_wait<1>();
        } else {
            cp_wait<0>();
        }
        __syncthreads();

        const uint32_t sb = smem + (uint32_t)(kt & 1) * STAGE_BYTES;
#pragma unroll
        for (int ks = 0; ks < 2; ++ks) {
            uint32_t aH[4][4], bH[4][2];
#pragma unroll
            for (int i = 0; i < 4; ++i)
                ldsm4(lds_addr(sb, wm * 64 + i * 16, ks, lane),
                      aH[i][0], aH[i][1], aH[i][2], aH[i][3]);
#pragma unroll
            for (int j2 = 0; j2 < 2; ++j2) {
                uint32_t r0, r1, r2, r3;
                ldsm4(lds_addr(sb + 8192, wn * 32 + j2 * 16, ks, lane), r0, r1, r2, r3);
                bH[j2 * 2 + 0][0] = r0; bH[j2 * 2 + 0][1] = r2;
                bH[j2 * 2 + 1][0] = r1; bH[j2 * 2 + 1][1] = r3;
            }
#pragma unroll
            for (int i = 0; i < 4; ++i)
#pragma unroll
                for (int j = 0; j < 4; ++j)
                    mma16816(acc[i][j], aH[i], bH[j][0], bH[j][1]);
        }
        __syncthreads();
    }

    // epilogue
    const size_t growb = (size_t)bm * 128 + wm * 64;
    const int    gcolb = bn * 128 + wn * 32;
#pragma unroll
    for (int i = 0; i < 4; ++i) {
        const size_t r0 = growb + i * 16 + (lane >> 2);
        float br0 = 0.f, br1 = 0.f;
        if (BIAS == 2) { br0 = bias[r0]; br1 = bias[r0 + 8]; }
#pragma unroll
        for (int j = 0; j < 4; ++j) {
            const int col = gcolb + j * 8 + (lane & 3) * 2;
            float c0 = 0.f, c1 = 0.f;
            if (BIAS == 1) { c0 = bias[col]; c1 = bias[col + 1]; }
            const float v00 = acc[i][j][0] * alpha + (BIAS == 2 ? br0 : c0);
            const float v01 = acc[i][j][1] * alpha + (BIAS == 2 ? br0 : c1);
            const float v10 = acc[i][j][2] * alpha + (BIAS == 2 ? br1 : c0);
            const float v11 = acc[i][j][3] * alpha + (BIAS == 2 ? br1 : c1);
            const size_t o0 = (size_t)z * sC + r0 * N + col;
            const size_t o1 = o0 + (size_t)8 * N;
            if (OUTMODE == 0) {
                *reinterpret_cast<float2*>(Cf + o0) = make_float2(v00, v01);
                *reinterpret_cast<float2*>(Cf + o1) = make_float2(v10, v11);
            } else {
                *reinterpret_cast<__half2*>(Ch + o0) =
                    __halves2half2(__float2half_rn(v00), __float2half_rn(v01));
                *reinterpret_cast<__half2*>(Ch + o1) =
                    __halves2half2(__float2half_rn(v10), __float2half_rn(v11));
            }
        }
    }
}

// ---------------------------------------------------------------------------
// fp32 -> fp16 convert (for X), vectorized by 4
// ---------------------------------------------------------------------------
__global__ __launch_bounds__(256) void to_half(
    const float4* __restrict__ in, __half* __restrict__ h, size_t n4)
{
    size_t i = (size_t)blockIdx.x * blockDim.x + threadIdx.x;
    if (i >= n4) return;
    float4 v = in[i];
    __align__(8) __half hb[4];
    hb[0] = __float2half_rn(v.x);
    hb[1] = __float2half_rn(v.y);
    hb[2] = __float2half_rn(v.z);
    hb[3] = __float2half_rn(v.w);
    reinterpret_cast<uint2*>(h)[i] = *reinterpret_cast<uint2*>(hb);
}

// ---------------------------------------------------------------------------
// All 4 weight transposes in ONE launch (z selects the weight), hi only.
// ---------------------------------------------------------------------------
__global__ __launch_bounds__(256) void transpose_weights(
    const float* __restrict__ W0, const float* __restrict__ W1,
    const float* __restrict__ W2, const float* __restrict__ W3,
    __half* __restrict__ H0, __half* __restrict__ H1,
    __half* __restrict__ H2, __half* __restrict__ H3)
{
    __shared__ float t[32][33];
    const int zi = blockIdx.z;
    const float* in = (zi == 0) ? W0 : (zi == 1) ? W1 : (zi == 2) ? W2 : W3;
    __half* hT = (zi == 0) ? H0 : (zi == 1) ? H1 : (zi == 2) ? H2 : H3;

    const int r0 = blockIdx.y * 32, c0 = blockIdx.x * 32;
    const int tx = threadIdx.x, ty = threadIdx.y;   // (32, 8)
#pragma unroll
    for (int j = 0; j < 4; ++j)
        t[ty + 8 * j][tx] = in[(size_t)(r0 + ty + 8 * j) * HID + c0 + tx];
    __syncthreads();
#pragma unroll
    for (int j = 0; j < 4; ++j) {
        size_t o = (size_t)(c0 + ty + 8 * j) * HID + r0 + tx;
        hT[o] = __float2half_rn(t[tx][ty + 8 * j]);
    }
}

// ---------------------------------------------------------------------------
// Row softmax over 2048 cols, fp32 in, fp16 out.
// ---------------------------------------------------------------------------
__global__ __launch_bounds__(256) void softmax_h(
    const float* __restrict__ Sf, __half* __restrict__ Sh)
{
    const size_t base = (size_t)blockIdx.x * SEQ;
    const int tid = threadIdx.x;

    float v[8];
    float m = -INFINITY;
#pragma unroll
    for (int i = 0; i < 8; ++i) {
        v[i] = Sf[base + tid + i * 256];
        m = fmaxf(m, v[i]);
    }

    __shared__ float red[256];
    red[tid] = m;
    __syncthreads();
#pragma unroll
    for (int s = 128; s > 0; s >>= 1) {
        if (tid < s) red[tid] = fmaxf(red[tid], red[tid + s]);
        __syncthreads();
    }
    m = red[0];
    __syncthreads();

    float sum = 0.f;
#pragma unroll
    for (int i = 0; i < 8; ++i) {
        v[i] = expf(v[i] - m);
        sum += v[i];
    }
    red[tid] = sum;
    __syncthreads();
#pragma unroll
    for (int s = 128; s > 0; s >>= 1) {
        if (tid < s) red[tid] += red[tid + s];
        __syncthreads();
    }
    const float inv = 1.0f / red[0];
#pragma unroll
    for (int i = 0; i < 8; ++i)
        Sh[base + tid + i * 256] = __float2half_rn(v[i] * inv);
}

// ---------------------------------------------------------------------------
extern "C" void kernel_launch(void* const* d_in, const int* in_sizes, int n_in,
                              void* d_out, int out_size)
{
    (void)in_sizes; (void)n_in; (void)out_size;

    const float* X  = (const float*)d_in[0];
    const float* Wq = (const float*)d_in[1];
    const float* bq = (const float*)d_in[2];
    const float* Wk = (const float*)d_in[3];
    const float* bk = (const float*)d_in[4];
    const float* Wv = (const float*)d_in[5];
    const float* bv = (const float*)d_in[6];
    const float* Wh = (const float*)d_in[7];
    const float* bh = (const float*)d_in[8];
    float* out = (float*)d_out;

    __half *Xh, *Wqh, *Wkh, *Wvh, *Whh;
    __half *Qh, *Kh, *Vth, *Sh, *Ch;
    float *Sf;
    cudaGetSymbolAddress((void**)&Xh,  g_Xh);
    cudaGetSymbolAddress((void**)&Wqh, g_Wqh);
    cudaGetSymbolAddress((void**)&Wkh, g_Wkh);
    cudaGetSymbolAddress((void**)&Wvh, g_Wvh);
    cudaGetSymbolAddress((void**)&Whh, g_Whh);
    cudaGetSymbolAddress((void**)&Qh,  g_Qh);
    cudaGetSymbolAddress((void**)&Kh,  g_Kh);
    cudaGetSymbolAddress((void**)&Vth, g_Vth);
    cudaGetSymbolAddress((void**)&Sf,  g_Sf);
    cudaGetSymbolAddress((void**)&Sh,  g_Sh);
    cudaGetSymbolAddress((void**)&Ch,  g_Ch);

    cudaFuncSetAttribute(gemm_h<0,0>, cudaFuncAttributeMaxDynamicSharedMemorySize, GEMM_SMEM);
    cudaFuncSetAttribute(gemm_h<0,1>, cudaFuncAttributeMaxDynamicSharedMemorySize, GEMM_SMEM);
    cudaFuncSetAttribute(gemm_h<1,0>, cudaFuncAttributeMaxDynamicSharedMemorySize, GEMM_SMEM);
    cudaFuncSetAttribute(gemm_h<1,1>, cudaFuncAttributeMaxDynamicSharedMemorySize, GEMM_SMEM);
    cudaFuncSetAttribute(gemm_h<1,2>, cudaFuncAttributeMaxDynamicSharedMemorySize, GEMM_SMEM);

    const dim3 blk(256);
    const float scale = 1.0f / 32.0f;   // 1/sqrt(1024)

    // launch 0: X -> fp16
    to_half<<<(MTOT * HID / 4 + 255) / 256, blk>>>(
        (const float4*)X, Xh, (size_t)MTOT * HID / 4);

    // launch 1: weight transposes (z-batched), hi only
    dim3 tgw(HID / 32, HID / 32, 4), tblk(32, 8);
    transpose_weights<<<tgw, tblk>>>(Wq, Wk, Wv, Wh, Wqh, Wkh, Wvh, Whh);

    // launches 2-3: Q, K projections (M=8192, N=1024, K=1024), col bias, fp16 out
    dim3 gp(HID / 128, MTOT / 128, 1);
    gemm_h<1,1><<<gp, blk, GEMM_SMEM>>>(Xh, Wqh, bq, nullptr, Qh,
                                        HID, HID, 0, 0, 0, 1.f);
    gemm_h<1,1><<<gp, blk, GEMM_SMEM>>>(Xh, Wkh, bk, nullptr, Kh,
                                        HID, HID, 0, 0, 0, 1.f);

    // launch 4: V^T = Wv^T @ X^T directly (per batch), ROW bias, fp16 out
    //   A = Wvh [HID, HID]; B = Xh batch-z rows [SEQ, HID]; C = Vth [HID, SEQ]
    dim3 gv(SEQ / 128, HID / 128, BATCH);
    gemm_h<1,2><<<gv, blk, GEMM_SMEM>>>(Wvh, Xh, bv, nullptr, Vth,
                                        SEQ, HID,
                                        0, (size_t)SEQ * HID, (size_t)HID * SEQ, 1.f);

    // launch 5 (ncu target): scores = scale * Q @ K^T (batched) -> fp32
    dim3 gs(SEQ / 128, SEQ / 128, BATCH);
    gemm_h<0,0><<<gs, blk, GEMM_SMEM>>>(Qh, Kh, nullptr, Sf, nullptr,
                                        SEQ, HID,
                                        (size_t)SEQ * HID, (size_t)SEQ * HID,
                                        (size_t)SEQ * SEQ, scale);

    // launch 6: softmax -> fp16
    softmax_h<<<BATCH * SEQ, blk>>>(Sf, Sh);

    // launch 7: context = attn @ V (batched, K=2048) -> fp16
    dim3 gc(HID / 128, SEQ / 128, BATCH);
    gemm_h<1,0><<<gc, blk, GEMM_SMEM>>>(Sh, Vth, nullptr, nullptr, Ch,
                                        HID, SEQ,
                                        (size_t)SEQ * SEQ, (size_t)HID * SEQ,
                                        (size_t)SEQ * HID, 1.f);

    // launch 8: y = context @ Wh + bh -> d_out fp32
    dim3 go(HID / 128, MTOT / 128, 1);
    gemm_h<0,1><<<go, blk, GEMM_SMEM>>>(Ch, Whh, bh, out, nullptr,
                                        HID, HID, 0, 0, 0, 1.f);
}

// round 11
// speedup vs baseline: 2.8497x; 1.1254x over previous
#include <cuda_runtime.h>
#include <cuda_fp16.h>
#include <math.h>
#include <stdint.h>

#define BATCH 4
#define SEQ   2048
#define HID   1024
#define MTOT  (BATCH * SEQ)   // 8192

// ---------------------------------------------------------------------------
// Scratch (device globals; allocation-free per harness rules)
// ---------------------------------------------------------------------------
__device__ __half g_Xh[(size_t)MTOT * HID];

__device__ __half g_Wqh[HID * HID];
__device__ __half g_Wkh[HID * HID];
__device__ __half g_Wvh[HID * HID];
__device__ __half g_Whh[HID * HID];

__device__ __half g_Qh[(size_t)MTOT * HID];
__device__ __half g_Kh[(size_t)MTOT * HID];
__device__ __half g_Vth[(size_t)MTOT * HID];   // per-batch [HID, SEQ]

__device__ float  g_Sf[(size_t)BATCH * SEQ * SEQ];
__device__ __half g_Sh[(size_t)BATCH * SEQ * SEQ];

__device__ __half g_Ch[(size_t)MTOT * HID];

// ---------------------------------------------------------------------------
// helpers
// ---------------------------------------------------------------------------
__device__ __forceinline__ uint32_t smem_u32(const void* p) {
    uint32_t a;
    asm("{ .reg .u64 t; cvta.to.shared.u64 t, %1; cvt.u32.u64 %0, t; }"
        : "=r"(a) : "l"(p));
    return a;
}

__device__ __forceinline__ void cp16(uint32_t saddr, const void* gaddr) {
    asm volatile("cp.async.cg.shared.global [%0], [%1], 16;"
                 :: "r"(saddr), "l"(gaddr));
}
__device__ __forceinline__ void cp_commit() {
    asm volatile("cp.async.commit_group;" ::: "memory");
}
template <int N>
__device__ __forceinline__ void cp_wait() {
    asm volatile("cp.async.wait_group %0;" :: "n"(N) : "memory");
}

__device__ __forceinline__ void ldsm4(uint32_t addr, uint32_t& r0, uint32_t& r1,
                                      uint32_t& r2, uint32_t& r3) {
    asm volatile("ldmatrix.sync.aligned.m8n8.x4.shared.b16 {%0,%1,%2,%3}, [%4];"
                 : "=r"(r0), "=r"(r1), "=r"(r2), "=r"(r3) : "r"(addr));
}

__device__ __forceinline__ void mma16816(float* c, const uint32_t* a,
                                         uint32_t b0, uint32_t b1) {
    asm volatile(
        "mma.sync.aligned.m16n8k16.row.col.f32.f16.f16.f32 "
        "{%0,%1,%2,%3}, {%4,%5,%6,%7}, {%8,%9}, {%0,%1,%2,%3};"
        : "+f"(c[0]), "+f"(c[1]), "+f"(c[2]), "+f"(c[3])
        : "r"(a[0]), "r"(a[1]), "r"(a[2]), "r"(a[3]), "r"(b0), "r"(b1));
}

// ldmatrix x4 source address inside a [128 rows x 128B] swizzled tile.
// base_row: first row of the 16x16 block; ks: k-step (0..3); lane: 0..31
__device__ __forceinline__ uint32_t lds_addr128(uint32_t tb, int base_row, int ks, int lane) {
    int r = base_row + ((lane >> 3) & 1) * 8 + (lane & 7);
    int c = (ks * 2 + (lane >> 4)) ^ (r & 7);
    return tb + (uint32_t)(r * 128 + c * 16);
}

// ---------------------------------------------------------------------------
// fp16 NT GEMM (fp32 accum): C[M,N] = alpha*(A @ B^T) + bias
//   A:[M,K] fp16 K-major; B:[N,K] fp16 K-major
// Block 128x128, Ktile 64 (128B swizzled rows), 8 warps (64x32 warp tile),
// 2-stage cp.async ring (issue next stage BEFORE waiting — proven schedule).
// OUTMODE: 0 = fp32, 1 = fp16.  BIAS: 0 = none, 1 = per-col, 2 = per-row.
// ---------------------------------------------------------------------------
#define STAGE_BYTES 32768u   // A 16KB + B 16KB
#define GEMM_SMEM   65536    // 2 stages

template <int OUTMODE, int BIAS>
__global__ __launch_bounds__(256) void gemm_h(
    const __half* __restrict__ Ap, const __half* __restrict__ Bp,
    const float* __restrict__ bias,
    float* __restrict__ Cf, __half* __restrict__ Ch,
    int N, int K, size_t sA, size_t sB, size_t sC, float alpha)
{
    extern __shared__ char smem_raw[];
    const uint32_t smem = smem_u32(smem_raw);

    const int tid  = threadIdx.x;
    const int lane = tid & 31;
    const int warp = tid >> 5;
    const int wm = warp >> 2;          // 0..1  (M)
    const int wn = warp & 3;           // 0..3  (N)
    const int bn = blockIdx.x, bm = blockIdx.y, z = blockIdx.z;

    const __half* pA = Ap + (size_t)z * sA + (size_t)bm * 128 * K;
    const __half* pB = Bp + (size_t)z * sB + (size_t)bn * 128 * K;

    // per-thread cp.async mapping: 128 rows x 8 chunks of 16B per tile,
    // 1024 chunks/tile, 256 threads -> 4 chunks/thread/tile.
    auto stage_load = [&](uint32_t sb, int k0) {
#pragma unroll
        for (int h = 0; h < 4; ++h) {
            const int ch  = tid + h * 256;        // 0..1023
            const int row = ch >> 3, c = ch & 7;
            const int cs  = c ^ (row & 7);
            const uint32_t so = (uint32_t)(row * 128 + cs * 16);
            const size_t   go = (size_t)row * K + k0 + c * 8;
            cp16(sb +     0 + so, pA + go);
            cp16(sb + 16384 + so, pB + go);
        }
    };

    float acc[4][4][4];
#pragma unroll
    for (int i = 0; i < 4; ++i)
#pragma unroll
        for (int j = 0; j < 4; ++j)
#pragma unroll
            for (int q = 0; q < 4; ++q) acc[i][j][q] = 0.f;

    const int KT = K >> 6;   // K-tiles of 64 (K = 1024 or 2048)

    stage_load(smem, 0);
    cp_commit();

    for (int kt = 0; kt < KT; ++kt) {
        // issue next stage FIRST (loads in flight while waiting), then wait
        if (kt + 1 < KT) {
            stage_load(smem + (uint32_t)((kt + 1) & 1) * STAGE_BYTES, (kt + 1) * 64);
            cp_commit();
            cp_wait<1>();
        } else {
            cp_wait<0>();
        }
        __syncthreads();

        const uint32_t sb = smem + (uint32_t)(kt & 1) * STAGE_BYTES;
#pragma unroll
        for (int ks = 0; ks < 4; ++ks) {
            uint32_t aH[4][4], bH[4][2];
#pragma unroll
            for (int i = 0; i < 4; ++i)
                ldsm4(lds_addr128(sb, wm * 64 + i * 16, ks, lane),
                      aH[i][0], aH[i][1], aH[i][2], aH[i][3]);
#pragma unroll
            for (int j2 = 0; j2 < 2; ++j2) {
                uint32_t r0, r1, r2, r3;
                ldsm4(lds_addr128(sb + 16384, wn * 32 + j2 * 16, ks, lane), r0, r1, r2, r3);
                bH[j2 * 2 + 0][0] = r0; bH[j2 * 2 + 0][1] = r2;
                bH[j2 * 2 + 1][0] = r1; bH[j2 * 2 + 1][1] = r3;
            }
#pragma unroll
            for (int i = 0; i < 4; ++i)
#pragma unroll
                for (int j = 0; j < 4; ++j)
                    mma16816(acc[i][j], aH[i], bH[j][0], bH[j][1]);
        }
        __syncthreads();
    }

    // epilogue
    const size_t growb = (size_t)bm * 128 + wm * 64;
    const int    gcolb = bn * 128 + wn * 32;
#pragma unroll
    for (int i = 0; i < 4; ++i) {
        const size_t r0 = growb + i * 16 + (lane >> 2);
        float br0 = 0.f, br1 = 0.f;
        if (BIAS == 2) { br0 = bias[r0]; br1 = bias[r0 + 8]; }
#pragma unroll
        for (int j = 0; j < 4; ++j) {
            const int col = gcolb + j * 8 + (lane & 3) * 2;
            float c0 = 0.f, c1 = 0.f;
            if (BIAS == 1) { c0 = bias[col]; c1 = bias[col + 1]; }
            const float v00 = acc[i][j][0] * alpha + (BIAS == 2 ? br0 : c0);
            const float v01 = acc[i][j][1] * alpha + (BIAS == 2 ? br0 : c1);
            const float v10 = acc[i][j][2] * alpha + (BIAS == 2 ? br1 : c0);
            const float v11 = acc[i][j][3] * alpha + (BIAS == 2 ? br1 : c1);
            const size_t o0 = (size_t)z * sC + r0 * N + col;
            const size_t o1 = o0 + (size_t)8 * N;
            if (OUTMODE == 0) {
                *reinterpret_cast<float2*>(Cf + o0) = make_float2(v00, v01);
                *reinterpret_cast<float2*>(Cf + o1) = make_float2(v10, v11);
            } else {
                *reinterpret_cast<__half2*>(Ch + o0) =
                    __halves2half2(__float2half_rn(v00), __float2half_rn(v01));
                *reinterpret_cast<__half2*>(Ch + o1) =
                    __halves2half2(__float2half_rn(v10), __float2half_rn(v11));
            }
        }
    }
}

// ---------------------------------------------------------------------------
// fp32 -> fp16 convert (for X), vectorized by 4
// ---------------------------------------------------------------------------
__global__ __launch_bounds__(256) void to_half(
    const float4* __restrict__ in, __half* __restrict__ h, size_t n4)
{
    size_t i = (size_t)blockIdx.x * blockDim.x + threadIdx.x;
    if (i >= n4) return;
    float4 v = in[i];
    __align__(8) __half hb[4];
    hb[0] = __float2half_rn(v.x);
    hb[1] = __float2half_rn(v.y);
    hb[2] = __float2half_rn(v.z);
    hb[3] = __float2half_rn(v.w);
    reinterpret_cast<uint2*>(h)[i] = *reinterpret_cast<uint2*>(hb);
}

// ---------------------------------------------------------------------------
// All 4 weight transposes in ONE launch (z selects the weight), hi only.
// ---------------------------------------------------------------------------
__global__ __launch_bounds__(256) void transpose_weights(
    const float* __restrict__ W0, const float* __restrict__ W1,
    const float* __restrict__ W2, const float* __restrict__ W3,
    __half* __restrict__ H0, __half* __restrict__ H1,
    __half* __restrict__ H2, __half* __restrict__ H3)
{
    __shared__ float t[32][33];
    const int zi = blockIdx.z;
    const float* in = (zi == 0) ? W0 : (zi == 1) ? W1 : (zi == 2) ? W2 : W3;
    __half* hT = (zi == 0) ? H0 : (zi == 1) ? H1 : (zi == 2) ? H2 : H3;

    const int r0 = blockIdx.y * 32, c0 = blockIdx.x * 32;
    const int tx = threadIdx.x, ty = threadIdx.y;   // (32, 8)
#pragma unroll
    for (int j = 0; j < 4; ++j)
        t[ty + 8 * j][tx] = in[(size_t)(r0 + ty + 8 * j) * HID + c0 + tx];
    __syncthreads();
#pragma unroll
    for (int j = 0; j < 4; ++j) {
        size_t o = (size_t)(c0 + ty + 8 * j) * HID + r0 + tx;
        hT[o] = __float2half_rn(t[tx][ty + 8 * j]);
    }
}

// ---------------------------------------------------------------------------
// Row softmax over 2048 cols, fp32 in, fp16 out.
// ---------------------------------------------------------------------------
__global__ __launch_bounds__(256) void softmax_h(
    const float* __restrict__ Sf, __half* __restrict__ Sh)
{
    const size_t base = (size_t)blockIdx.x * SEQ;
    const int tid = threadIdx.x;

    float v[8];
    float m = -INFINITY;
#pragma unroll
    for (int i = 0; i < 8; ++i) {
        v[i] = Sf[base + tid + i * 256];
        m = fmaxf(m, v[i]);
    }

    __shared__ float red[256];
    red[tid] = m;
    __syncthreads();
#pragma unroll
    for (int s = 128; s > 0; s >>= 1) {
        if (tid < s) red[tid] = fmaxf(red[tid], red[tid + s]);
        __syncthreads();
    }
    m = red[0];
    __syncthreads();

    float sum = 0.f;
#pragma unroll
    for (int i = 0; i < 8; ++i) {
        v[i] = expf(v[i] - m);
        sum += v[i];
    }
    red[tid] = sum;
    __syncthreads();
#pragma unroll
    for (int s = 128; s > 0; s >>= 1) {
        if (tid < s) red[tid] += red[tid + s];
        __syncthreads();
    }
    const float inv = 1.0f / red[0];
#pragma unroll
    for (int i = 0; i < 8; ++i)
        Sh[base + tid + i * 256] = __float2half_rn(v[i] * inv);
}

// ---------------------------------------------------------------------------
extern "C" void kernel_launch(void* const* d_in, const int* in_sizes, int n_in,
                              void* d_out, int out_size)
{
    (void)in_sizes; (void)n_in; (void)out_size;

    const float* X  = (const float*)d_in[0];
    const float* Wq = (const float*)d_in[1];
    const float* bq = (const float*)d_in[2];
    const float* Wk = (const float*)d_in[3];
    const float* bk = (const float*)d_in[4];
    const float* Wv = (const float*)d_in[5];
    const float* bv = (const float*)d_in[6];
    const float* Wh = (const float*)d_in[7];
    const float* bh = (const float*)d_in[8];
    float* out = (float*)d_out;

    __half *Xh, *Wqh, *Wkh, *Wvh, *Whh;
    __half *Qh, *Kh, *Vth, *Sh, *Ch;
    float *Sf;
    cudaGetSymbolAddress((void**)&Xh,  g_Xh);
    cudaGetSymbolAddress((void**)&Wqh, g_Wqh);
    cudaGetSymbolAddress((void**)&Wkh, g_Wkh);
    cudaGetSymbolAddress((void**)&Wvh, g_Wvh);
    cudaGetSymbolAddress((void**)&Whh, g_Whh);
    cudaGetSymbolAddress((void**)&Qh,  g_Qh);
    cudaGetSymbolAddress((void**)&Kh,  g_Kh);
    cudaGetSymbolAddress((void**)&Vth, g_Vth);
    cudaGetSymbolAddress((void**)&Sf,  g_Sf);
    cudaGetSymbolAddress((void**)&Sh,  g_Sh);
    cudaGetSymbolAddress((void**)&Ch,  g_Ch);

    cudaFuncSetAttribute(gemm_h<0,0>, cudaFuncAttributeMaxDynamicSharedMemorySize, GEMM_SMEM);
    cudaFuncSetAttribute(gemm_h<0,1>, cudaFuncAttributeMaxDynamicSharedMemorySize, GEMM_SMEM);
    cudaFuncSetAttribute(gemm_h<1,0>, cudaFuncAttributeMaxDynamicSharedMemorySize, GEMM_SMEM);
    cudaFuncSetAttribute(gemm_h<1,1>, cudaFuncAttributeMaxDynamicSharedMemorySize, GEMM_SMEM);
    cudaFuncSetAttribute(gemm_h<1,2>, cudaFuncAttributeMaxDynamicSharedMemorySize, GEMM_SMEM);

    const dim3 blk(256);
    const float scale = 1.0f / 32.0f;   // 1/sqrt(1024)

    // launch 0: X -> fp16
    to_half<<<(MTOT * HID / 4 + 255) / 256, blk>>>(
        (const float4*)X, Xh, (size_t)MTOT * HID / 4);

    // launch 1: weight transposes (z-batched), hi only
    dim3 tgw(HID / 32, HID / 32, 4), tblk(32, 8);
    transpose_weights<<<tgw, tblk>>>(Wq, Wk, Wv, Wh, Wqh, Wkh, Wvh, Whh);

    // launches 2-3: Q, K projections (M=8192, N=1024, K=1024), col bias, fp16 out
    dim3 gp(HID / 128, MTOT / 128, 1);
    gemm_h<1,1><<<gp, blk, GEMM_SMEM>>>(Xh, Wqh, bq, nullptr, Qh,
                                        HID, HID, 0, 0, 0, 1.f);
    gemm_h<1,1><<<gp, blk, GEMM_SMEM>>>(Xh, Wkh, bk, nullptr, Kh,
                                        HID, HID, 0, 0, 0, 1.f);

    // launch 4: V^T = Wv^T @ X^T directly (per batch), ROW bias, fp16 out
    //   A = Wvh [HID, HID]; B = Xh batch-z rows [SEQ, HID]; C = Vth [HID, SEQ]
    dim3 gv(SEQ / 128, HID / 128, BATCH);
    gemm_h<1,2><<<gv, blk, GEMM_SMEM>>>(Wvh, Xh, bv, nullptr, Vth,
                                        SEQ, HID,
                                        0, (size_t)SEQ * HID, (size_t)HID * SEQ, 1.f);

    // launch 5 (ncu target): scores = scale * Q @ K^T (batched) -> fp32
    dim3 gs(SEQ / 128, SEQ / 128, BATCH);
    gemm_h<0,0><<<gs, blk, GEMM_SMEM>>>(Qh, Kh, nullptr, Sf, nullptr,
                                        SEQ, HID,
                                        (size_t)SEQ * HID, (size_t)SEQ * HID,
                                        (size_t)SEQ * SEQ, scale);

    // launch 6: softmax -> fp16
    softmax_h<<<BATCH * SEQ, blk>>>(Sf, Sh);

    // launch 7: context = attn @ V (batched, K=2048) -> fp16
    dim3 gc(HID / 128, SEQ / 128, BATCH);
    gemm_h<1,0><<<gc, blk, GEMM_SMEM>>>(Sh, Vth, nullptr, nullptr, Ch,
                                        HID, SEQ,
                                        (size_t)SEQ * SEQ, (size_t)HID * SEQ,
                                        (size_t)SEQ * HID, 1.f);

    // launch 8: y = context @ Wh + bh -> d_out fp32
    dim3 go(HID / 128, MTOT / 128, 1);
    gemm_h<0,1><<<go, blk, GEMM_SMEM>>>(Ch, Whh, bh, out, nullptr,
                                        HID, HID, 0, 0, 0, 1.f);
}

// round 12
// speedup vs baseline: 2.9574x; 1.0378x over previous
#include <cuda_runtime.h>
#include <cuda_fp16.h>
#include <math.h>
#include <stdint.h>

#define BATCH 4
#define SEQ   2048
#define HID   1024
#define MTOT  (BATCH * SEQ)   // 8192

// ---------------------------------------------------------------------------
// Scratch (device globals; allocation-free per harness rules)
// ---------------------------------------------------------------------------
__device__ __half g_Xh[(size_t)MTOT * HID];

__device__ __half g_Wqkh[2 * HID * HID];   // [0]=Wq^T, [1]=Wk^T
__device__ float  g_bqk[2 * HID];          // [0]=bq,  [1]=bk
__device__ __half g_Wvh[HID * HID];
__device__ __half g_Whh[HID * HID];

__device__ __half g_QKh[(size_t)2 * MTOT * HID];  // [0]=Q, [1]=K
__device__ __half g_Vth[(size_t)MTOT * HID];      // per-batch [HID, SEQ]

__device__ __half g_Ssc[(size_t)BATCH * SEQ * SEQ];  // raw scores (fp16)
__device__ __half g_Sh[(size_t)BATCH * SEQ * SEQ];   // softmax probs (fp16)

__device__ __half g_Ch[(size_t)MTOT * HID];

// ---------------------------------------------------------------------------
// helpers
// ---------------------------------------------------------------------------
__device__ __forceinline__ uint32_t smem_u32(const void* p) {
    uint32_t a;
    asm("{ .reg .u64 t; cvta.to.shared.u64 t, %1; cvt.u32.u64 %0, t; }"
        : "=r"(a) : "l"(p));
    return a;
}

__device__ __forceinline__ void cp16(uint32_t saddr, const void* gaddr) {
    asm volatile("cp.async.cg.shared.global [%0], [%1], 16;"
                 :: "r"(saddr), "l"(gaddr));
}
__device__ __forceinline__ void cp_commit() {
    asm volatile("cp.async.commit_group;" ::: "memory");
}
template <int N>
__device__ __forceinline__ void cp_wait() {
    asm volatile("cp.async.wait_group %0;" :: "n"(N) : "memory");
}

__device__ __forceinline__ void ldsm4(uint32_t addr, uint32_t& r0, uint32_t& r1,
                                      uint32_t& r2, uint32_t& r3) {
    asm volatile("ldmatrix.sync.aligned.m8n8.x4.shared.b16 {%0,%1,%2,%3}, [%4];"
                 : "=r"(r0), "=r"(r1), "=r"(r2), "=r"(r3) : "r"(addr));
}

__device__ __forceinline__ void mma16816(float* c, const uint32_t* a,
                                         uint32_t b0, uint32_t b1) {
    asm volatile(
        "mma.sync.aligned.m16n8k16.row.col.f32.f16.f16.f32 "
        "{%0,%1,%2,%3}, {%4,%5,%6,%7}, {%8,%9}, {%0,%1,%2,%3};"
        : "+f"(c[0]), "+f"(c[1]), "+f"(c[2]), "+f"(c[3])
        : "r"(a[0]), "r"(a[1]), "r"(a[2]), "r"(a[3]), "r"(b0), "r"(b1));
}

// ldmatrix x4 source address inside a [128 rows x 128B] swizzled tile.
__device__ __forceinline__ uint32_t lds_addr128(uint32_t tb, int base_row, int ks, int lane) {
    int r = base_row + ((lane >> 3) & 1) * 8 + (lane & 7);
    int c = (ks * 2 + (lane >> 4)) ^ (r & 7);
    return tb + (uint32_t)(r * 128 + c * 16);
}

// ---------------------------------------------------------------------------
// fp16 NT GEMM (fp32 accum): C[M,N] = alpha*(A @ B^T) + bias
//   A:[M,K] fp16 K-major; B:[N,K] fp16 K-major; z-strides for A/B/C/bias.
// Block 128x128, Ktile 64 (128B swizzled rows), 8 warps (64x32 warp tile),
// 2-stage cp.async ring (issue next stage BEFORE waiting — proven schedule).
// OUTMODE: 0 = fp32, 1 = fp16.  BIAS: 0 = none, 1 = per-col, 2 = per-row.
// ---------------------------------------------------------------------------
#define STAGE_BYTES 32768u   // A 16KB + B 16KB
#define GEMM_SMEM   65536    // 2 stages

template <int OUTMODE, int BIAS>
__global__ __launch_bounds__(256) void gemm_h(
    const __half* __restrict__ Ap, const __half* __restrict__ Bp,
    const float* __restrict__ bias,
    float* __restrict__ Cf, __half* __restrict__ Ch,
    int N, int K, size_t sA, size_t sB, size_t sC, size_t sBias, float alpha)
{
    extern __shared__ char smem_raw[];
    const uint32_t smem = smem_u32(smem_raw);

    const int tid  = threadIdx.x;
    const int lane = tid & 31;
    const int warp = tid >> 5;
    const int wm = warp >> 2;          // 0..1  (M)
    const int wn = warp & 3;           // 0..3  (N)
    const int bn = blockIdx.x, bm = blockIdx.y, z = blockIdx.z;

    const __half* pA = Ap + (size_t)z * sA + (size_t)bm * 128 * K;
    const __half* pB = Bp + (size_t)z * sB + (size_t)bn * 128 * K;
    if (BIAS) bias += (size_t)z * sBias;

    // per-thread cp.async mapping: 128 rows x 8 chunks of 16B per tile.
    auto stage_load = [&](uint32_t sb, int k0) {
#pragma unroll
        for (int h = 0; h < 4; ++h) {
            const int ch  = tid + h * 256;        // 0..1023
            const int row = ch >> 3, c = ch & 7;
            const int cs  = c ^ (row & 7);
            const uint32_t so = (uint32_t)(row * 128 + cs * 16);
            const size_t   go = (size_t)row * K + k0 + c * 8;
            cp16(sb +     0 + so, pA + go);
            cp16(sb + 16384 + so, pB + go);
        }
    };

    float acc[4][4][4];
#pragma unroll
    for (int i = 0; i < 4; ++i)
#pragma unroll
        for (int j = 0; j < 4; ++j)
#pragma unroll
            for (int q = 0; q < 4; ++q) acc[i][j][q] = 0.f;

    const int KT = K >> 6;

    stage_load(smem, 0);
    cp_commit();

    for (int kt = 0; kt < KT; ++kt) {
        // issue next stage FIRST (loads in flight while waiting), then wait
        if (kt + 1 < KT) {
            stage_load(smem + (uint32_t)((kt + 1) & 1) * STAGE_BYTES, (kt + 1) * 64);
            cp_commit();
            cp_wait<1>();
        } else {
            cp_wait<0>();
        }
        __syncthreads();

        const uint32_t sb = smem + (uint32_t)(kt & 1) * STAGE_BYTES;
#pragma unroll
        for (int ks = 0; ks < 4; ++ks) {
            uint32_t aH[4][4], bH[4][2];
#pragma unroll
            for (int i = 0; i < 4; ++i)
                ldsm4(lds_addr128(sb, wm * 64 + i * 16, ks, lane),
                      aH[i][0], aH[i][1], aH[i][2], aH[i][3]);
#pragma unroll
            for (int j2 = 0; j2 < 2; ++j2) {
                uint32_t r0, r1, r2, r3;
                ldsm4(lds_addr128(sb + 16384, wn * 32 + j2 * 16, ks, lane), r0, r1, r2, r3);
                bH[j2 * 2 + 0][0] = r0; bH[j2 * 2 + 0][1] = r2;
                bH[j2 * 2 + 1][0] = r1; bH[j2 * 2 + 1][1] = r3;
            }
#pragma unroll
            for (int i = 0; i < 4; ++i)
#pragma unroll
                for (int j = 0; j < 4; ++j)
                    mma16816(acc[i][j], aH[i], bH[j][0], bH[j][1]);
        }
        __syncthreads();
    }

    // epilogue
    const size_t growb = (size_t)bm * 128 + wm * 64;
    const int    gcolb = bn * 128 + wn * 32;
#pragma unroll
    for (int i = 0; i < 4; ++i) {
        const size_t r0 = growb + i * 16 + (lane >> 2);
        float br0 = 0.f, br1 = 0.f;
        if (BIAS == 2) { br0 = bias[r0]; br1 = bias[r0 + 8]; }
#pragma unroll
        for (int j = 0; j < 4; ++j) {
            const int col = gcolb + j * 8 + (lane & 3) * 2;
            float c0 = 0.f, c1 = 0.f;
            if (BIAS == 1) { c0 = bias[col]; c1 = bias[col + 1]; }
            const float v00 = acc[i][j][0] * alpha + (BIAS == 2 ? br0 : c0);
            const float v01 = acc[i][j][1] * alpha + (BIAS == 2 ? br0 : c1);
            const float v10 = acc[i][j][2] * alpha + (BIAS == 2 ? br1 : c0);
            const float v11 = acc[i][j][3] * alpha + (BIAS == 2 ? br1 : c1);
            const size_t o0 = (size_t)z * sC + r0 * N + col;
            const size_t o1 = o0 + (size_t)8 * N;
            if (OUTMODE == 0) {
                *reinterpret_cast<float2*>(Cf + o0) = make_float2(v00, v01);
                *reinterpret_cast<float2*>(Cf + o1) = make_float2(v10, v11);
            } else {
                *reinterpret_cast<__half2*>(Ch + o0) =
                    __halves2half2(__float2half_rn(v00), __float2half_rn(v01));
                *reinterpret_cast<__half2*>(Ch + o1) =
                    __halves2half2(__float2half_rn(v10), __float2half_rn(v11));
            }
        }
    }
}

// ---------------------------------------------------------------------------
// fp32 -> fp16 convert (for X), vectorized by 4
// ---------------------------------------------------------------------------
__global__ __launch_bounds__(256) void to_half(
    const float4* __restrict__ in, __half* __restrict__ h, size_t n4)
{
    size_t i = (size_t)blockIdx.x * blockDim.x + threadIdx.x;
    if (i >= n4) return;
    float4 v = in[i];
    __align__(8) __half hb[4];
    hb[0] = __float2half_rn(v.x);
    hb[1] = __float2half_rn(v.y);
    hb[2] = __float2half_rn(v.z);
    hb[3] = __float2half_rn(v.w);
    reinterpret_cast<uint2*>(h)[i] = *reinterpret_cast<uint2*>(hb);
}

// ---------------------------------------------------------------------------
// All 4 weight transposes in ONE launch (z selects the weight), hi only.
// Wq->g_Wqkh[0], Wk->g_Wqkh[1], Wv->g_Wvh, Wh->g_Whh.
// Block (0,0,z=0) additionally packs bq|bk into g_bqk.
// ---------------------------------------------------------------------------
__global__ __launch_bounds__(256) void transpose_weights(
    const float* __restrict__ W0, const float* __restrict__ W1,
    const float* __restrict__ W2, const float* __restrict__ W3,
    const float* __restrict__ bq, const float* __restrict__ bk,
    __half* __restrict__ Hqk, __half* __restrict__ H2, __half* __restrict__ H3,
    float* __restrict__ bqk)
{
    __shared__ float t[32][33];
    const int zi = blockIdx.z;
    const float* in = (zi == 0) ? W0 : (zi == 1) ? W1 : (zi == 2) ? W2 : W3;
    __half* hT = (zi == 0) ? Hqk : (zi == 1) ? (Hqk + (size_t)HID * HID)
                : (zi == 2) ? H2 : H3;

    const int tid = threadIdx.y * 32 + threadIdx.x;
    if (zi == 0 && blockIdx.x == 0 && blockIdx.y == 0) {
#pragma unroll
        for (int q = 0; q < 4; ++q) {
            int idx = tid + q * 256;   // 0..1023
            bqk[idx] = bq[idx];
            bqk[HID + idx] = bk[idx];
        }
    }

    const int r0 = blockIdx.y * 32, c0 = blockIdx.x * 32;
    const int tx = threadIdx.x, ty = threadIdx.y;   // (32, 8)
#pragma unroll
    for (int j = 0; j < 4; ++j)
        t[ty + 8 * j][tx] = in[(size_t)(r0 + ty + 8 * j) * HID + c0 + tx];
    __syncthreads();
#pragma unroll
    for (int j = 0; j < 4; ++j) {
        size_t o = (size_t)(c0 + ty + 8 * j) * HID + r0 + tx;
        hT[o] = __float2half_rn(t[tx][ty + 8 * j]);
    }
}

// ---------------------------------------------------------------------------
// Row softmax over 2048 cols, fp16 in, fp16 out (fp32 internal).
// ---------------------------------------------------------------------------
__global__ __launch_bounds__(256) void softmax_h(
    const __half* __restrict__ Ssc, __half* __restrict__ Sh)
{
    const size_t base = (size_t)blockIdx.x * SEQ;
    const int tid = threadIdx.x;
    const __half2* in2 = reinterpret_cast<const __half2*>(Ssc + base);
    __half2* out2 = reinterpret_cast<__half2*>(Sh + base);

    float v[8];
    float m = -INFINITY;
#pragma unroll
    for (int i = 0; i < 4; ++i) {
        float2 p = __half22float2(in2[tid + i * 256]);
        v[2 * i] = p.x; v[2 * i + 1] = p.y;
        m = fmaxf(m, fmaxf(p.x, p.y));
    }

    __shared__ float red[256];
    red[tid] = m;
    __syncthreads();
#pragma unroll
    for (int s = 128; s > 0; s >>= 1) {
        if (tid < s) red[tid] = fmaxf(red[tid], red[tid + s]);
        __syncthreads();
    }
    m = red[0];
    __syncthreads();

    float sum = 0.f;
#pragma unroll
    for (int i = 0; i < 8; ++i) {
        v[i] = expf(v[i] - m);
        sum += v[i];
    }
    red[tid] = sum;
    __syncthreads();
#pragma unroll
    for (int s = 128; s > 0; s >>= 1) {
        if (tid < s) red[tid] += red[tid + s];
        __syncthreads();
    }
    const float inv = 1.0f / red[0];
#pragma unroll
    for (int i = 0; i < 4; ++i)
        out2[tid + i * 256] = __floats2half2_rn(v[2 * i] * inv, v[2 * i + 1] * inv);
}

// ---------------------------------------------------------------------------
extern "C" void kernel_launch(void* const* d_in, const int* in_sizes, int n_in,
                              void* d_out, int out_size)
{
    (void)in_sizes; (void)n_in; (void)out_size;

    const float* X  = (const float*)d_in[0];
    const float* Wq = (const float*)d_in[1];
    const float* bq = (const float*)d_in[2];
    const float* Wk = (const float*)d_in[3];
    const float* bk = (const float*)d_in[4];
    const float* Wv = (const float*)d_in[5];
    const float* bv = (const float*)d_in[6];
    const float* Wh = (const float*)d_in[7];
    const float* bh = (const float*)d_in[8];
    float* out = (float*)d_out;

    __half *Xh, *Wqkh, *Wvh, *Whh, *QKh, *Vth, *Ssc, *Sh, *Ch;
    float *bqk;
    cudaGetSymbolAddress((void**)&Xh,   g_Xh);
    cudaGetSymbolAddress((void**)&Wqkh, g_Wqkh);
    cudaGetSymbolAddress((void**)&bqk,  g_bqk);
    cudaGetSymbolAddress((void**)&Wvh,  g_Wvh);
    cudaGetSymbolAddress((void**)&Whh,  g_Whh);
    cudaGetSymbolAddress((void**)&QKh,  g_QKh);
    cudaGetSymbolAddress((void**)&Vth,  g_Vth);
    cudaGetSymbolAddress((void**)&Ssc,  g_Ssc);
    cudaGetSymbolAddress((void**)&Sh,   g_Sh);
    cudaGetSymbolAddress((void**)&Ch,   g_Ch);

    __half* Qh = QKh;
    __half* Kh = QKh + (size_t)MTOT * HID;

    cudaFuncSetAttribute(gemm_h<0,1>, cudaFuncAttributeMaxDynamicSharedMemorySize, GEMM_SMEM);
    cudaFuncSetAttribute(gemm_h<1,0>, cudaFuncAttributeMaxDynamicSharedMemorySize, GEMM_SMEM);
    cudaFuncSetAttribute(gemm_h<1,1>, cudaFuncAttributeMaxDynamicSharedMemorySize, GEMM_SMEM);
    cudaFuncSetAttribute(gemm_h<1,2>, cudaFuncAttributeMaxDynamicSharedMemorySize, GEMM_SMEM);

    const dim3 blk(256);
    const float scale = 1.0f / 32.0f;   // 1/sqrt(1024)

    // launch 0: X -> fp16
    to_half<<<(MTOT * HID / 4 + 255) / 256, blk>>>(
        (const float4*)X, Xh, (size_t)MTOT * HID / 4);

    // launch 1: weight transposes (z-batched) + bias pack
    dim3 tgw(HID / 32, HID / 32, 4), tblk(32, 8);
    transpose_weights<<<tgw, tblk>>>(Wq, Wk, Wv, Wh, bq, bk,
                                     Wqkh, Wvh, Whh, bqk);

    // launch 2: MERGED Q+K projections (z=0 -> Q, z=1 -> K), col bias, fp16 out
    dim3 gqk(HID / 128, MTOT / 128, 2);
    gemm_h<1,1><<<gqk, blk, GEMM_SMEM>>>(Xh, Wqkh, bqk, nullptr, QKh,
                                         HID, HID,
                                         0, (size_t)HID * HID, (size_t)MTOT * HID,
                                         HID, 1.f);

    // launch 3: V^T = Wv^T @ X^T directly (per batch), ROW bias, fp16 out
    dim3 gv(SEQ / 128, HID / 128, BATCH);
    gemm_h<1,2><<<gv, blk, GEMM_SMEM>>>(Wvh, Xh, bv, nullptr, Vth,
                                        SEQ, HID,
                                        0, (size_t)SEQ * HID, (size_t)HID * SEQ,
                                        0, 1.f);

    // launch 4: scores = scale * Q @ K^T (batched) -> fp16
    dim3 gs(SEQ / 128, SEQ / 128, BATCH);
    gemm_h<1,0><<<gs, blk, GEMM_SMEM>>>(Qh, Kh, nullptr, nullptr, Ssc,
                                        SEQ, HID,
                                        (size_t)SEQ * HID, (size_t)SEQ * HID,
                                        (size_t)SEQ * SEQ, 0, scale);

    // launch 5 (ncu target): softmax fp16 -> fp16
    softmax_h<<<BATCH * SEQ, blk>>>(Ssc, Sh);

    // launch 6: context = attn @ V (batched, K=2048) -> fp16
    dim3 gc(HID / 128, SEQ / 128, BATCH);
    gemm_h<1,0><<<gc, blk, GEMM_SMEM>>>(Sh, Vth, nullptr, nullptr, Ch,
                                        HID, SEQ,
                                        (size_t)SEQ * SEQ, (size_t)HID * SEQ,
                                        (size_t)SEQ * HID, 0, 1.f);

    // launch 7: y = context @ Wh + bh -> d_out fp32
    dim3 go(HID / 128, MTOT / 128, 1);
    gemm_h<0,1><<<go, blk, GEMM_SMEM>>>(Ch, Whh, bh, out, nullptr,
                                        HID, HID, 0, 0, 0, 0, 1.f);
}

// round 13
// speedup vs baseline: 3.0763x; 1.0402x over previous
#include <cuda_runtime.h>
#include <cuda_fp16.h>
#include <math.h>
#include <stdint.h>

#define BATCH 4
#define SEQ   2048
#define HID   1024
#define MTOT  (BATCH * SEQ)   // 8192
#define SCALE (1.0f / 32.0f)  // 1/sqrt(1024)

// ---------------------------------------------------------------------------
// Scratch (device globals; allocation-free per harness rules)
// ---------------------------------------------------------------------------
__device__ __half g_Xh[(size_t)MTOT * HID];

__device__ __half g_Wqr[HID * HID];    // Wq raw (row-major), fp16
__device__ __half g_Wkr[HID * HID];    // Wk raw (row-major), fp16
__device__ __half g_Wvh[HID * HID];    // Wv^T, fp16
__device__ __half g_Whh[HID * HID];    // Wh^T, fp16

__device__ __half g_MT[HID * HID];     // MT = Wk @ Wq^T, fp16
__device__ float  g_w2[HID];           // w2 = Wk @ bq
__device__ float  g_v[MTOT];           // v = (X @ w2) / 32

__device__ __half g_Ah[(size_t)MTOT * HID];       // A = X @ M (fp16)
__device__ __half g_Vth[(size_t)MTOT * HID];      // per-batch [HID, SEQ]

__device__ __half g_Ssc[(size_t)BATCH * SEQ * SEQ];  // raw scores (fp16)
__device__ __half g_Sh[(size_t)BATCH * SEQ * SEQ];   // softmax probs (fp16)

__device__ __half g_Ch[(size_t)MTOT * HID];

// ---------------------------------------------------------------------------
// helpers
// ---------------------------------------------------------------------------
__device__ __forceinline__ uint32_t smem_u32(const void* p) {
    uint32_t a;
    asm("{ .reg .u64 t; cvta.to.shared.u64 t, %1; cvt.u32.u64 %0, t; }"
        : "=r"(a) : "l"(p));
    return a;
}

__device__ __forceinline__ void cp16(uint32_t saddr, const void* gaddr) {
    asm volatile("cp.async.cg.shared.global [%0], [%1], 16;"
                 :: "r"(saddr), "l"(gaddr));
}
__device__ __forceinline__ void cp_commit() {
    asm volatile("cp.async.commit_group;" ::: "memory");
}
template <int N>
__device__ __forceinline__ void cp_wait() {
    asm volatile("cp.async.wait_group %0;" :: "n"(N) : "memory");
}

__device__ __forceinline__ void ldsm4(uint32_t addr, uint32_t& r0, uint32_t& r1,
                                      uint32_t& r2, uint32_t& r3) {
    asm volatile("ldmatrix.sync.aligned.m8n8.x4.shared.b16 {%0,%1,%2,%3}, [%4];"
                 : "=r"(r0), "=r"(r1), "=r"(r2), "=r"(r3) : "r"(addr));
}

__device__ __forceinline__ void mma16816(float* c, const uint32_t* a,
                                         uint32_t b0, uint32_t b1) {
    asm volatile(
        "mma.sync.aligned.m16n8k16.row.col.f32.f16.f16.f32 "
        "{%0,%1,%2,%3}, {%4,%5,%6,%7}, {%8,%9}, {%0,%1,%2,%3};"
        : "+f"(c[0]), "+f"(c[1]), "+f"(c[2]), "+f"(c[3])
        : "r"(a[0]), "r"(a[1]), "r"(a[2]), "r"(a[3]), "r"(b0), "r"(b1));
}

// ldmatrix x4 source address inside a [128 rows x 128B] swizzled tile.
__device__ __forceinline__ uint32_t lds_addr128(uint32_t tb, int base_row, int ks, int lane) {
    int r = base_row + ((lane >> 3) & 1) * 8 + (lane & 7);
    int c = (ks * 2 + (lane >> 4)) ^ (r & 7);
    return tb + (uint32_t)(r * 128 + c * 16);
}

// ---------------------------------------------------------------------------
// fp16 NT GEMM (fp32 accum): C[M,N] = alpha*(A @ B^T) + bias
//   A:[M,K] fp16 K-major; B:[N,K] fp16 K-major; z-strides for A/B/C/bias.
// Block 128x128, Ktile 64 (128B swizzled rows), 8 warps (64x32 warp tile),
// 2-stage cp.async ring (issue next stage BEFORE waiting — proven schedule).
// OUTMODE: 0 = fp32, 1 = fp16.  BIAS: 0 = none, 1 = per-col, 2 = per-row.
// ---------------------------------------------------------------------------
#define STAGE_BYTES 32768u   // A 16KB + B 16KB
#define GEMM_SMEM   65536    // 2 stages

template <int OUTMODE, int BIAS>
__global__ __launch_bounds__(256) void gemm_h(
    const __half* __restrict__ Ap, const __half* __restrict__ Bp,
    const float* __restrict__ bias,
    float* __restrict__ Cf, __half* __restrict__ Ch,
    int N, int K, size_t sA, size_t sB, size_t sC, size_t sBias, float alpha)
{
    extern __shared__ char smem_raw[];
    const uint32_t smem = smem_u32(smem_raw);

    const int tid  = threadIdx.x;
    const int lane = tid & 31;
    const int warp = tid >> 5;
    const int wm = warp >> 2;          // 0..1  (M)
    const int wn = warp & 3;           // 0..3  (N)
    const int bn = blockIdx.x, bm = blockIdx.y, z = blockIdx.z;

    const __half* pA = Ap + (size_t)z * sA + (size_t)bm * 128 * K;
    const __half* pB = Bp + (size_t)z * sB + (size_t)bn * 128 * K;
    if (BIAS) bias += (size_t)z * sBias;

    auto stage_load = [&](uint32_t sb, int k0) {
#pragma unroll
        for (int h = 0; h < 4; ++h) {
            const int ch  = tid + h * 256;        // 0..1023
            const int row = ch >> 3, c = ch & 7;
            const int cs  = c ^ (row & 7);
            const uint32_t so = (uint32_t)(row * 128 + cs * 16);
            const size_t   go = (size_t)row * K + k0 + c * 8;
            cp16(sb +     0 + so, pA + go);
            cp16(sb + 16384 + so, pB + go);
        }
    };

    float acc[4][4][4];
#pragma unroll
    for (int i = 0; i < 4; ++i)
#pragma unroll
        for (int j = 0; j < 4; ++j)
#pragma unroll
            for (int q = 0; q < 4; ++q) acc[i][j][q] = 0.f;

    const int KT = K >> 6;

    stage_load(smem, 0);
    cp_commit();

    for (int kt = 0; kt < KT; ++kt) {
        // issue next stage FIRST (loads in flight while waiting), then wait
        if (kt + 1 < KT) {
            stage_load(smem + (uint32_t)((kt + 1) & 1) * STAGE_BYTES, (kt + 1) * 64);
            cp_commit();
            cp_wait<1>();
        } else {
            cp_wait<0>();
        }
        __syncthreads();

        const uint32_t sb = smem + (uint32_t)(kt & 1) * STAGE_BYTES;
#pragma unroll
        for (int ks = 0; ks < 4; ++ks) {
            uint32_t aH[4][4], bH[4][2];
#pragma unroll
            for (int i = 0; i < 4; ++i)
                ldsm4(lds_addr128(sb, wm * 64 + i * 16, ks, lane),
                      aH[i][0], aH[i][1], aH[i][2], aH[i][3]);
#pragma unroll
            for (int j2 = 0; j2 < 2; ++j2) {
                uint32_t r0, r1, r2, r3;
                ldsm4(lds_addr128(sb + 16384, wn * 32 + j2 * 16, ks, lane), r0, r1, r2, r3);
                bH[j2 * 2 + 0][0] = r0; bH[j2 * 2 + 0][1] = r2;
                bH[j2 * 2 + 1][0] = r1; bH[j2 * 2 + 1][1] = r3;
            }
#pragma unroll
            for (int i = 0; i < 4; ++i)
#pragma unroll
                for (int j = 0; j < 4; ++j)
                    mma16816(acc[i][j], aH[i], bH[j][0], bH[j][1]);
        }
        __syncthreads();
    }

    // epilogue
    const size_t growb = (size_t)bm * 128 + wm * 64;
    const int    gcolb = bn * 128 + wn * 32;
#pragma unroll
    for (int i = 0; i < 4; ++i) {
        const size_t r0 = growb + i * 16 + (lane >> 2);
        float br0 = 0.f, br1 = 0.f;
        if (BIAS == 2) { br0 = bias[r0]; br1 = bias[r0 + 8]; }
#pragma unroll
        for (int j = 0; j < 4; ++j) {
            const int col = gcolb + j * 8 + (lane & 3) * 2;
            float c0 = 0.f, c1 = 0.f;
            if (BIAS == 1) { c0 = bias[col]; c1 = bias[col + 1]; }
            const float v00 = acc[i][j][0] * alpha + (BIAS == 2 ? br0 : c0);
            const float v01 = acc[i][j][1] * alpha + (BIAS == 2 ? br0 : c1);
            const float v10 = acc[i][j][2] * alpha + (BIAS == 2 ? br1 : c0);
            const float v11 = acc[i][j][3] * alpha + (BIAS == 2 ? br1 : c1);
            const size_t o0 = (size_t)z * sC + r0 * N + col;
            const size_t o1 = o0 + (size_t)8 * N;
            if (OUTMODE == 0) {
                *reinterpret_cast<float2*>(Cf + o0) = make_float2(v00, v01);
                *reinterpret_cast<float2*>(Cf + o1) = make_float2(v10, v11);
            } else {
                *reinterpret_cast<__half2*>(Ch + o0) =
                    __halves2half2(__float2half_rn(v00), __float2half_rn(v01));
                *reinterpret_cast<__half2*>(Ch + o1) =
                    __halves2half2(__float2half_rn(v10), __float2half_rn(v11));
            }
        }
    }
}

// ---------------------------------------------------------------------------
// Weight prep (z selects): z=0 Wq raw->fp16, z=1 Wk raw->fp16,
// z=2 Wv transpose->fp16, z=3 Wh transpose->fp16.
// ---------------------------------------------------------------------------
__global__ __launch_bounds__(256) void convert_weights(
    const float* __restrict__ W0, const float* __restrict__ W1,
    const float* __restrict__ W2, const float* __restrict__ W3,
    __half* __restrict__ H0, __half* __restrict__ H1,
    __half* __restrict__ H2, __half* __restrict__ H3)
{
    __shared__ float t[32][33];
    const int zi = blockIdx.z;
    const float* in = (zi == 0) ? W0 : (zi == 1) ? W1 : (zi == 2) ? W2 : W3;
    __half* hO = (zi == 0) ? H0 : (zi == 1) ? H1 : (zi == 2) ? H2 : H3;

    const int r0 = blockIdx.y * 32, c0 = blockIdx.x * 32;
    const int tx = threadIdx.x, ty = threadIdx.y;   // (32, 8)
#pragma unroll
    for (int j = 0; j < 4; ++j)
        t[ty + 8 * j][tx] = in[(size_t)(r0 + ty + 8 * j) * HID + c0 + tx];
    __syncthreads();
    if (zi < 2) {
        // elementwise convert (no transpose)
#pragma unroll
        for (int j = 0; j < 4; ++j) {
            size_t o = (size_t)(r0 + ty + 8 * j) * HID + c0 + tx;
            hO[o] = __float2half_rn(t[ty + 8 * j][tx]);
        }
    } else {
        // transposed convert
#pragma unroll
        for (int j = 0; j < 4; ++j) {
            size_t o = (size_t)(c0 + ty + 8 * j) * HID + r0 + tx;
            hO[o] = __float2half_rn(t[tx][ty + 8 * j]);
        }
    }
}

// ---------------------------------------------------------------------------
// w2[k] = sum_i Wk[k][i] * bq[i]  (one block per k)
// ---------------------------------------------------------------------------
__global__ __launch_bounds__(256) void gemv_w2(
    const float* __restrict__ Wk, const float* __restrict__ bq,
    float* __restrict__ w2)
{
    const int k = blockIdx.x, tid = threadIdx.x;
    float s = 0.f;
#pragma unroll
    for (int q = 0; q < 4; ++q) {
        int i = tid + q * 256;
        s += Wk[(size_t)k * HID + i] * bq[i];
    }
    __shared__ float red[256];
    red[tid] = s;
    __syncthreads();
#pragma unroll
    for (int st = 128; st > 0; st >>= 1) {
        if (tid < st) red[tid] += red[tid + st];
        __syncthreads();
    }
    if (tid == 0) w2[k] = red[0];
}

// ---------------------------------------------------------------------------
// X row -> fp16 + v[m] = (X_m . w2) * SCALE.  One block per row.
// ---------------------------------------------------------------------------
__global__ __launch_bounds__(256) void to_half_v(
    const float* __restrict__ X, const float* __restrict__ w2,
    __half* __restrict__ Xh, float* __restrict__ v)
{
    const int m = blockIdx.x, tid = threadIdx.x;
    const size_t base = (size_t)m * HID;
    float4 val = reinterpret_cast<const float4*>(X + base)[tid];

    __align__(8) __half hb[4];
    hb[0] = __float2half_rn(val.x);
    hb[1] = __float2half_rn(val.y);
    hb[2] = __float2half_rn(val.z);
    hb[3] = __float2half_rn(val.w);
    reinterpret_cast<uint2*>(Xh + base)[tid] = *reinterpret_cast<uint2*>(hb);

    const float4 wv = reinterpret_cast<const float4*>(w2)[tid];
    float s = val.x * wv.x + val.y * wv.y + val.z * wv.z + val.w * wv.w;
    __shared__ float red[256];
    red[tid] = s;
    __syncthreads();
#pragma unroll
    for (int st = 128; st > 0; st >>= 1) {
        if (tid < st) red[tid] += red[tid + st];
        __syncthreads();
    }
    if (tid == 0) v[m] = red[0] * SCALE;
}

// ---------------------------------------------------------------------------
// Row softmax over 2048 cols, fp16 in, fp16 out (fp32 internal).
// ---------------------------------------------------------------------------
__global__ __launch_bounds__(256) void softmax_h(
    const __half* __restrict__ Ssc, __half* __restrict__ Sh)
{
    const size_t base = (size_t)blockIdx.x * SEQ;
    const int tid = threadIdx.x;
    const __half2* in2 = reinterpret_cast<const __half2*>(Ssc + base);
    __half2* out2 = reinterpret_cast<__half2*>(Sh + base);

    float v[8];
    float m = -INFINITY;
#pragma unroll
    for (int i = 0; i < 4; ++i) {
        float2 p = __half22float2(in2[tid + i * 256]);
        v[2 * i] = p.x; v[2 * i + 1] = p.y;
        m = fmaxf(m, fmaxf(p.x, p.y));
    }

    __shared__ float red[256];
    red[tid] = m;
    __syncthreads();
#pragma unroll
    for (int s = 128; s > 0; s >>= 1) {
        if (tid < s) red[tid] = fmaxf(red[tid], red[tid + s]);
        __syncthreads();
    }
    m = red[0];
    __syncthreads();

    float sum = 0.f;
#pragma unroll
    for (int i = 0; i < 8; ++i) {
        v[i] = expf(v[i] - m);
        sum += v[i];
    }
    red[tid] = sum;
    __syncthreads();
#pragma unroll
    for (int s = 128; s > 0; s >>= 1) {
        if (tid < s) red[tid] += red[tid + s];
        __syncthreads();
    }
    const float inv = 1.0f / red[0];
#pragma unroll
    for (int i = 0; i < 4; ++i)
        out2[tid + i * 256] = __floats2half2_rn(v[2 * i] * inv, v[2 * i + 1] * inv);
}

// ---------------------------------------------------------------------------
extern "C" void kernel_launch(void* const* d_in, const int* in_sizes, int n_in,
                              void* d_out, int out_size)
{
    (void)in_sizes; (void)n_in; (void)out_size;

    const float* X  = (const float*)d_in[0];
    const float* Wq = (const float*)d_in[1];
    const float* bq = (const float*)d_in[2];
    const float* Wk = (const float*)d_in[3];
    const float* bk = (const float*)d_in[4];   // cancels in softmax (row-const)
    const float* Wv = (const float*)d_in[5];
    const float* bv = (const float*)d_in[6];
    const float* Wh = (const float*)d_in[7];
    const float* bh = (const float*)d_in[8];
    float* out = (float*)d_out;
    (void)bk;

    __half *Xh, *Wqr, *Wkr, *Wvh, *Whh, *MT, *Ah, *Vth, *Ssc, *Sh, *Ch;
    float *w2, *v;
    cudaGetSymbolAddress((void**)&Xh,  g_Xh);
    cudaGetSymbolAddress((void**)&Wqr, g_Wqr);
    cudaGetSymbolAddress((void**)&Wkr, g_Wkr);
    cudaGetSymbolAddress((void**)&Wvh, g_Wvh);
    cudaGetSymbolAddress((void**)&Whh, g_Whh);
    cudaGetSymbolAddress((void**)&MT,  g_MT);
    cudaGetSymbolAddress((void**)&w2,  g_w2);
    cudaGetSymbolAddress((void**)&v,   g_v);
    cudaGetSymbolAddress((void**)&Ah,  g_Ah);
    cudaGetSymbolAddress((void**)&Vth, g_Vth);
    cudaGetSymbolAddress((void**)&Ssc, g_Ssc);
    cudaGetSymbolAddress((void**)&Sh,  g_Sh);
    cudaGetSymbolAddress((void**)&Ch,  g_Ch);

    cudaFuncSetAttribute(gemm_h<0,1>, cudaFuncAttributeMaxDynamicSharedMemorySize, GEMM_SMEM);
    cudaFuncSetAttribute(gemm_h<1,0>, cudaFuncAttributeMaxDynamicSharedMemorySize, GEMM_SMEM);
    cudaFuncSetAttribute(gemm_h<1,1>, cudaFuncAttributeMaxDynamicSharedMemorySize, GEMM_SMEM);
    cudaFuncSetAttribute(gemm_h<1,2>, cudaFuncAttributeMaxDynamicSharedMemorySize, GEMM_SMEM);

    const dim3 blk(256);

    // L0: weight prep (Wq/Wk raw fp16; Wv/Wh transposed fp16)
    dim3 tgw(HID / 32, HID / 32, 4), tblk(32, 8);
    convert_weights<<<tgw, tblk>>>(Wq, Wk, Wv, Wh, Wqr, Wkr, Wvh, Whh);

    // L1: w2 = Wk @ bq
    gemv_w2<<<HID, blk>>>(Wk, bq, w2);

    // L2: X -> fp16 + v = (X @ w2) * scale  (one block per row)
    to_half_v<<<MTOT, blk>>>(X, w2, Xh, v);

    // L3: MT = Wk @ Wq^T  (fp16 out, grid 8x8)
    dim3 gm(HID / 128, HID / 128, 1);
    gemm_h<1,0><<<gm, blk, GEMM_SMEM>>>(Wkr, Wqr, nullptr, nullptr, MT,
                                        HID, HID, 0, 0, 0, 0, 1.f);

    // L4: V^T = Wv^T @ X^T (per batch), ROW bias, fp16 out
    dim3 gv(SEQ / 128, HID / 128, BATCH);
    gemm_h<1,2><<<gv, blk, GEMM_SMEM>>>(Wvh, Xh, bv, nullptr, Vth,
                                        SEQ, HID,
                                        0, (size_t)SEQ * HID, (size_t)HID * SEQ,
                                        0, 1.f);

    // L5: A = X @ M = X @ MT^T  (fp16 out)
    dim3 ga(HID / 128, MTOT / 128, 1);
    gemm_h<1,0><<<ga, blk, GEMM_SMEM>>>(Xh, MT, nullptr, nullptr, Ah,
                                        HID, HID, 0, 0, 0, 0, 1.f);

    // L6: scores = scale * (A @ X^T) + v_col  (batched; u,c cancel in softmax)
    dim3 gs(SEQ / 128, SEQ / 128, BATCH);
    gemm_h<1,1><<<gs, blk, GEMM_SMEM>>>(Ah, Xh, v, nullptr, Ssc,
                                        SEQ, HID,
                                        (size_t)SEQ * HID, (size_t)SEQ * HID,
                                        (size_t)SEQ * SEQ, SEQ, SCALE);

    // L7: softmax fp16 -> fp16
    softmax_h<<<BATCH * SEQ, blk>>>(Ssc, Sh);

    // L8: context = attn @ V (batched, K=2048) -> fp16
    dim3 gc(HID / 128, SEQ / 128, BATCH);
    gemm_h<1,0><<<gc, blk, GEMM_SMEM>>>(Sh, Vth, nullptr, nullptr, Ch,
                                        HID, SEQ,
                                        (size_t)SEQ * SEQ, (size_t)HID * SEQ,
                                        (size_t)SEQ * HID, 0, 1.f);

    // L9: y = context @ Wh + bh -> d_out fp32
    dim3 go(HID / 128, MTOT / 128, 1);
    gemm_h<0,1><<<go, blk, GEMM_SMEM>>>(Ch, Whh, bh, out, nullptr,
                                        HID, HID, 0, 0, 0, 0, 1.f);
}

// round 16
// speedup vs baseline: 3.1153x; 1.0127x over previous
#include <cuda_runtime.h>
#include <cuda_fp16.h>
#include <math.h>
#include <stdint.h>

#define BATCH 4
#define SEQ   2048
#define HID   1024
#define MTOT  (BATCH * SEQ)   // 8192
#define SCALE (1.0f / 32.0f)  // 1/sqrt(1024)

// ---------------------------------------------------------------------------
// Scratch (device globals; allocation-free per harness rules)
// ---------------------------------------------------------------------------
__device__ __half g_Xh[(size_t)MTOT * HID];

__device__ __half g_Wqr[HID * HID];    // Wq raw (row-major), fp16
__device__ __half g_Wkr[HID * HID];    // Wk raw (row-major), fp16
__device__ __half g_Wvh[HID * HID];    // Wv^T, fp16
__device__ __half g_Whh[HID * HID];    // Wh^T, fp16

__device__ float  g_MTp[(size_t)4 * HID * HID];  // split-K partials (fp32)
__device__ __half g_MT[HID * HID];     // MT = Wk @ Wq^T, fp16
__device__ float  g_w2[HID];           // w2 = Wk @ bq
__device__ float  g_v[MTOT];           // v = (X @ w2) / 32

__device__ __half g_Ah[(size_t)MTOT * HID];       // A = X @ M (fp16)
__device__ __half g_Vth[(size_t)MTOT * HID];      // per-batch [HID, SEQ]

__device__ __half g_Ssc[(size_t)BATCH * SEQ * SEQ];  // raw scores (fp16)
__device__ __half g_Sh[(size_t)BATCH * SEQ * SEQ];   // softmax probs (fp16)

__device__ __half g_Ch[(size_t)MTOT * HID];

// ---------------------------------------------------------------------------
// helpers
// ---------------------------------------------------------------------------
__device__ __forceinline__ uint32_t smem_u32(const void* p) {
    uint32_t a;
    asm("{ .reg .u64 t; cvta.to.shared.u64 t, %1; cvt.u32.u64 %0, t; }"
        : "=r"(a) : "l"(p));
    return a;
}

__device__ __forceinline__ void cp16(uint32_t saddr, const void* gaddr) {
    asm volatile("cp.async.cg.shared.global [%0], [%1], 16;"
                 :: "r"(saddr), "l"(gaddr));
}
__device__ __forceinline__ void cp_commit() {
    asm volatile("cp.async.commit_group;" ::: "memory");
}
template <int N>
__device__ __forceinline__ void cp_wait() {
    asm volatile("cp.async.wait_group %0;" :: "n"(N) : "memory");
}

__device__ __forceinline__ void ldsm4(uint32_t addr, uint32_t& r0, uint32_t& r1,
                                      uint32_t& r2, uint32_t& r3) {
    asm volatile("ldmatrix.sync.aligned.m8n8.x4.shared.b16 {%0,%1,%2,%3}, [%4];"
                 : "=r"(r0), "=r"(r1), "=r"(r2), "=r"(r3) : "r"(addr));
}

__device__ __forceinline__ void mma16816(float* c, const uint32_t* a,
                                         uint32_t b0, uint32_t b1) {
    asm volatile(
        "mma.sync.aligned.m16n8k16.row.col.f32.f16.f16.f32 "
        "{%0,%1,%2,%3}, {%4,%5,%6,%7}, {%8,%9}, {%0,%1,%2,%3};"
        : "+f"(c[0]), "+f"(c[1]), "+f"(c[2]), "+f"(c[3])
        : "r"(a[0]), "r"(a[1]), "r"(a[2]), "r"(a[3]), "r"(b0), "r"(b1));
}

// ldmatrix x4 source address inside a [128 rows x 128B] swizzled tile.
__device__ __forceinline__ uint32_t lds_addr128(uint32_t tb, int base_row, int ks, int lane) {
    int r = base_row + ((lane >> 3) & 1) * 8 + (lane & 7);
    int c = (ks * 2 + (lane >> 4)) ^ (r & 7);
    return tb + (uint32_t)(r * 128 + c * 16);
}

// ---------------------------------------------------------------------------
// fp16 NT GEMM (fp32 accum): C[M,N] = alpha*(A @ B^T) + bias
//   A:[M,*] fp16, ld = row stride (elements); K = reduction extent;
//   B:[N,*] fp16 same ld; z-strides for A/B/C/bias (sA/sB in ELEMENTS).
// Block 128x128, Ktile 64 (128B swizzled rows), 8 warps (64x32 warp tile).
// 3-stage cp.async ring, SAFE order: wait -> sync -> issue -> compute.
// (Issue happens after the barrier, so no warp can still be reading the
//  buffer being refilled — eliminates the R14 race. wait<1> is near-free
//  at depth 3 because stage kt was prefetched two iterations earlier.)
// OUTMODE: 0 = fp32, 1 = fp16.  BIAS: 0 = none, 1 = per-col, 2 = per-row.
// ---------------------------------------------------------------------------
#define STAGE_BYTES 32768u   // A 16KB + B 16KB
#define GEMM_SMEM   98304    // 3 stages

template <int OUTMODE, int BIAS>
__global__ __launch_bounds__(256) void gemm_h(
    const __half* __restrict__ Ap, const __half* __restrict__ Bp,
    const float* __restrict__ bias,
    float* __restrict__ Cf, __half* __restrict__ Ch,
    int N, int K, int ld,
    size_t sA, size_t sB, size_t sC, size_t sBias, float alpha)
{
    extern __shared__ char smem_raw[];
    const uint32_t smem = smem_u32(smem_raw);

    const int tid  = threadIdx.x;
    const int lane = tid & 31;
    const int warp = tid >> 5;
    const int wm = warp >> 2;          // 0..1  (M)
    const int wn = warp & 3;           // 0..3  (N)
    const int bn = blockIdx.x, bm = blockIdx.y, z = blockIdx.z;

    const __half* pA = Ap + (size_t)z * sA + (size_t)bm * 128 * ld;
    const __half* pB = Bp + (size_t)z * sB + (size_t)bn * 128 * ld;
    if (BIAS) bias += (size_t)z * sBias;

    auto stage_load = [&](uint32_t sb, int k0) {
#pragma unroll
        for (int h = 0; h < 4; ++h) {
            const int ch  = tid + h * 256;        // 0..1023
            const int row = ch >> 3, c = ch & 7;
            const int cs  = c ^ (row & 7);
            const uint32_t so = (uint32_t)(row * 128 + cs * 16);
            const size_t   go = (size_t)row * ld + k0 + c * 8;
            cp16(sb +     0 + so, pA + go);
            cp16(sb + 16384 + so, pB + go);
        }
    };

    float acc[4][4][4];
#pragma unroll
    for (int i = 0; i < 4; ++i)
#pragma unroll
        for (int j = 0; j < 4; ++j)
#pragma unroll
            for (int q = 0; q < 4; ++q) acc[i][j][q] = 0.f;

    const int KT = K >> 6;

    // prologue: stages 0 and 1 in flight (2 groups)
    stage_load(smem, 0);
    cp_commit();
    if (KT > 1) stage_load(smem + STAGE_BYTES, 64);
    cp_commit();

    int buf = 0;   // buffer of stage kt
    for (int kt = 0; kt < KT; ++kt) {
        cp_wait<1>();        // stage kt landed (only stage kt+1 may be pending)
        __syncthreads();     // ALL warps done reading the buffer to be refilled

        // safe to refill (kt+2)%3 now: its previous occupant (stage kt-1)
        // is fully consumed by every warp.
        if (kt + 2 < KT) {
            int nb = buf + 2; if (nb >= 3) nb -= 3;
            stage_load(smem + (uint32_t)nb * STAGE_BYTES, (kt + 2) * 64);
        }
        cp_commit();

        const uint32_t sb = smem + (uint32_t)buf * STAGE_BYTES;
#pragma unroll
        for (int ks = 0; ks < 4; ++ks) {
            uint32_t aH[4][4], bH[4][2];
#pragma unroll
            for (int i = 0; i < 4; ++i)
                ldsm4(lds_addr128(sb, wm * 64 + i * 16, ks, lane),
                      aH[i][0], aH[i][1], aH[i][2], aH[i][3]);
#pragma unroll
            for (int j2 = 0; j2 < 2; ++j2) {
                uint32_t r0, r1, r2, r3;
                ldsm4(lds_addr128(sb + 16384, wn * 32 + j2 * 16, ks, lane), r0, r1, r2, r3);
                bH[j2 * 2 + 0][0] = r0; bH[j2 * 2 + 0][1] = r2;
                bH[j2 * 2 + 1][0] = r1; bH[j2 * 2 + 1][1] = r3;
            }
#pragma unroll
            for (int i = 0; i < 4; ++i)
#pragma unroll
                for (int j = 0; j < 4; ++j)
                    mma16816(acc[i][j], aH[i], bH[j][0], bH[j][1]);
        }
        if (++buf == 3) buf = 0;
    }

    // epilogue
    const size_t growb = (size_t)bm * 128 + wm * 64;
    const int    gcolb = bn * 128 + wn * 32;
#pragma unroll
    for (int i = 0; i < 4; ++i) {
        const size_t r0 = growb + i * 16 + (lane >> 2);
        float br0 = 0.f, br1 = 0.f;
        if (BIAS == 2) { br0 = bias[r0]; br1 = bias[r0 + 8]; }
#pragma unroll
        for (int j = 0; j < 4; ++j) {
            const int col = gcolb + j * 8 + (lane & 3) * 2;
            float c0 = 0.f, c1 = 0.f;
            if (BIAS == 1) { c0 = bias[col]; c1 = bias[col + 1]; }
            const float v00 = acc[i][j][0] * alpha + (BIAS == 2 ? br0 : c0);
            const float v01 = acc[i][j][1] * alpha + (BIAS == 2 ? br0 : c1);
            const float v10 = acc[i][j][2] * alpha + (BIAS == 2 ? br1 : c0);
            const float v11 = acc[i][j][3] * alpha + (BIAS == 2 ? br1 : c1);
            const size_t o0 = (size_t)z * sC + r0 * N + col;
            const size_t o1 = o0 + (size_t)8 * N;
            if (OUTMODE == 0) {
                *reinterpret_cast<float2*>(Cf + o0) = make_float2(v00, v01);
                *reinterpret_cast<float2*>(Cf + o1) = make_float2(v10, v11);
            } else {
                *reinterpret_cast<__half2*>(Ch + o0) =
                    __halves2half2(__float2half_rn(v00), __float2half_rn(v01));
                *reinterpret_cast<__half2*>(Ch + o1) =
                    __halves2half2(__float2half_rn(v10), __float2half_rn(v11));
            }
        }
    }
}

// ---------------------------------------------------------------------------
// Weight prep (z selects): z=0 Wq raw->fp16, z=1 Wk raw->fp16,
// z=2 Wv transpose->fp16, z=3 Wh transpose->fp16.
// ---------------------------------------------------------------------------
__global__ __launch_bounds__(256) void convert_weights(
    const float* __restrict__ W0, const float* __restrict__ W1,
    const float* __restrict__ W2, const float* __restrict__ W3,
    __half* __restrict__ H0, __half* __restrict__ H1,
    __half* __restrict__ H2, __half* __restrict__ H3)
{
    __shared__ float t[32][33];
    const int zi = blockIdx.z;
    const float* in = (zi == 0) ? W0 : (zi == 1) ? W1 : (zi == 2) ? W2 : W3;
    __half* hO = (zi == 0) ? H0 : (zi == 1) ? H1 : (zi == 2) ? H2 : H3;

    const int r0 = blockIdx.y * 32, c0 = blockIdx.x * 32;
    const int tx = threadIdx.x, ty = threadIdx.y;   // (32, 8)
#pragma unroll
    for (int j = 0; j < 4; ++j)
        t[ty + 8 * j][tx] = in[(size_t)(r0 + ty + 8 * j) * HID + c0 + tx];
    __syncthreads();
    if (zi < 2) {
#pragma unroll
        for (int j = 0; j < 4; ++j) {
            size_t o = (size_t)(r0 + ty + 8 * j) * HID + c0 + tx;
            hO[o] = __float2half_rn(t[ty + 8 * j][tx]);
        }
    } else {
#pragma unroll
        for (int j = 0; j < 4; ++j) {
            size_t o = (size_t)(c0 + ty + 8 * j) * HID + r0 + tx;
            hO[o] = __float2half_rn(t[tx][ty + 8 * j]);
        }
    }
}

// ---------------------------------------------------------------------------
// Reduce split-K partials: MT = fp16(p0 + p1 + p2 + p3), vectorized by 4
// ---------------------------------------------------------------------------
__global__ __launch_bounds__(256) void reduce_mt(
    const float* __restrict__ p, __half* __restrict__ mt)
{
    const size_t S = (size_t)HID * HID;
    size_t i = ((size_t)blockIdx.x * 256 + threadIdx.x) * 4;
    float4 a = *reinterpret_cast<const float4*>(p + i);
    float4 b = *reinterpret_cast<const float4*>(p + S + i);
    float4 c = *reinterpret_cast<const float4*>(p + 2 * S + i);
    float4 d = *reinterpret_cast<const float4*>(p + 3 * S + i);
    __align__(8) __half hb[4];
    hb[0] = __float2half_rn(a.x + b.x + c.x + d.x);
    hb[1] = __float2half_rn(a.y + b.y + c.y + d.y);
    hb[2] = __float2half_rn(a.z + b.z + c.z + d.z);
    hb[3] = __float2half_rn(a.w + b.w + c.w + d.w);
    *reinterpret_cast<uint2*>(mt + i) = *reinterpret_cast<uint2*>(hb);
}

// ---------------------------------------------------------------------------
// w2[k] = sum_i Wk[k][i] * bq[i]  (one block per k)
// ---------------------------------------------------------------------------
__global__ __launch_bounds__(256) void gemv_w2(
    const float* __restrict__ Wk, const float* __restrict__ bq,
    float* __restrict__ w2)
{
    const int k = blockIdx.x, tid = threadIdx.x;
    float s = 0.f;
#pragma unroll
    for (int q = 0; q < 4; ++q) {
        int i = tid + q * 256;
        s += Wk[(size_t)k * HID + i] * bq[i];
    }
    __shared__ float red[256];
    red[tid] = s;
    __syncthreads();
#pragma unroll
    for (int st = 128; st > 0; st >>= 1) {
        if (tid < st) red[tid] += red[tid + st];
        __syncthreads();
    }
    if (tid == 0) w2[k] = red[0];
}

// ---------------------------------------------------------------------------
// X row -> fp16 + v[m] = (X_m . w2) * SCALE.  One block per row.
// ---------------------------------------------------------------------------
__global__ __launch_bounds__(256) void to_half_v(
    const float* __restrict__ X, const float* __restrict__ w2,
    __half* __restrict__ Xh, float* __restrict__ v)
{
    const int m = blockIdx.x, tid = threadIdx.x;
    const size_t base = (size_t)m * HID;
    float4 val = reinterpret_cast<const float4*>(X + base)[tid];

    __align__(8) __half hb[4];
    hb[0] = __float2half_rn(val.x);
    hb[1] = __float2half_rn(val.y);
    hb[2] = __float2half_rn(val.z);
    hb[3] = __float2half_rn(val.w);
    reinterpret_cast<uint2*>(Xh + base)[tid] = *reinterpret_cast<uint2*>(hb);

    const float4 wv = reinterpret_cast<const float4*>(w2)[tid];
    float s = val.x * wv.x + val.y * wv.y + val.z * wv.z + val.w * wv.w;
    __shared__ float red[256];
    red[tid] = s;
    __syncthreads();
#pragma unroll
    for (int st = 128; st > 0; st >>= 1) {
        if (tid < st) red[tid] += red[tid + st];
        __syncthreads();
    }
    if (tid == 0) v[m] = red[0] * SCALE;
}

// ---------------------------------------------------------------------------
// Row softmax over 2048 cols, fp16 in, fp16 out (fp32 internal).
// ---------------------------------------------------------------------------
__global__ __launch_bounds__(256) void softmax_h(
    const __half* __restrict__ Ssc, __half* __restrict__ Sh)
{
    const size_t base = (size_t)blockIdx.x * SEQ;
    const int tid = threadIdx.x;
    const __half2* in2 = reinterpret_cast<const __half2*>(Ssc + base);
    __half2* out2 = reinterpret_cast<__half2*>(Sh + base);

    float v[8];
    float m = -INFINITY;
#pragma unroll
    for (int i = 0; i < 4; ++i) {
        float2 p = __half22float2(in2[tid + i * 256]);
        v[2 * i] = p.x; v[2 * i + 1] = p.y;
        m = fmaxf(m, fmaxf(p.x, p.y));
    }

    __shared__ float red[256];
    red[tid] = m;
    __syncthreads();
#pragma unroll
    for (int s = 128; s > 0; s >>= 1) {
        if (tid < s) red[tid] = fmaxf(red[tid], red[tid + s]);
        __syncthreads();
    }
    m = red[0];
    __syncthreads();

    float sum = 0.f;
#pragma unroll
    for (int i = 0; i < 8; ++i) {
        v[i] = expf(v[i] - m);
        sum += v[i];
    }
    red[tid] = sum;
    __syncthreads();
#pragma unroll
    for (int s = 128; s > 0; s >>= 1) {
        if (tid < s) red[tid] += red[tid + s];
        __syncthreads();
    }
    const float inv = 1.0f / red[0];
#pragma unroll
    for (int i = 0; i < 4; ++i)
        out2[tid + i * 256] = __floats2half2_rn(v[2 * i] * inv, v[2 * i + 1] * inv);
}

// ---------------------------------------------------------------------------
extern "C" void kernel_launch(void* const* d_in, const int* in_sizes, int n_in,
                              void* d_out, int out_size)
{
    (void)in_sizes; (void)n_in; (void)out_size;

    const float* X  = (const float*)d_in[0];
    const float* Wq = (const float*)d_in[1];
    const float* bq = (const float*)d_in[2];
    const float* Wk = (const float*)d_in[3];
    const float* bk = (const float*)d_in[4];   // cancels in softmax (row-const)
    const float* Wv = (const float*)d_in[5];
    const float* bv = (const float*)d_in[6];
    const float* Wh = (const float*)d_in[7];
    const float* bh = (const float*)d_in[8];
    float* out = (float*)d_out;
    (void)bk;

    __half *Xh, *Wqr, *Wkr, *Wvh, *Whh, *MT, *Ah, *Vth, *Ssc, *Sh, *Ch;
    float *MTp, *w2, *v;
    cudaGetSymbolAddress((void**)&Xh,  g_Xh);
    cudaGetSymbolAddress((void**)&Wqr, g_Wqr);
    cudaGetSymbolAddress((void**)&Wkr, g_Wkr);
    cudaGetSymbolAddress((void**)&Wvh, g_Wvh);
    cudaGetSymbolAddress((void**)&Whh, g_Whh);
    cudaGetSymbolAddress((void**)&MTp, g_MTp);
    cudaGetSymbolAddress((void**)&MT,  g_MT);
    cudaGetSymbolAddress((void**)&w2,  g_w2);
    cudaGetSymbolAddress((void**)&v,   g_v);
    cudaGetSymbolAddress((void**)&Ah,  g_Ah);
    cudaGetSymbolAddress((void**)&Vth, g_Vth);
    cudaGetSymbolAddress((void**)&Ssc, g_Ssc);
    cudaGetSymbolAddress((void**)&Sh,  g_Sh);
    cudaGetSymbolAddress((void**)&Ch,  g_Ch);

    cudaFuncSetAttribute(gemm_h<0,0>, cudaFuncAttributeMaxDynamicSharedMemorySize, GEMM_SMEM);
    cudaFuncSetAttribute(gemm_h<0,1>, cudaFuncAttributeMaxDynamicSharedMemorySize, GEMM_SMEM);
    cudaFuncSetAttribute(gemm_h<1,0>, cudaFuncAttributeMaxDynamicSharedMemorySize, GEMM_SMEM);
    cudaFuncSetAttribute(gemm_h<1,1>, cudaFuncAttributeMaxDynamicSharedMemorySize, GEMM_SMEM);
    cudaFuncSetAttribute(gemm_h<1,2>, cudaFuncAttributeMaxDynamicSharedMemorySize, GEMM_SMEM);

    const dim3 blk(256);

    // L0: weight prep (Wq/Wk raw fp16; Wv/Wh transposed fp16)
    dim3 tgw(HID / 32, HID / 32, 4), tblk(32, 8);
    convert_weights<<<tgw, tblk>>>(Wq, Wk, Wv, Wh, Wqr, Wkr, Wvh, Whh);

    // L1: MT partials = Wk @ Wq^T, split-K over z (K=256 each) -> fp32
    dim3 gm(HID / 128, HID / 128, 4);
    gemm_h<0,0><<<gm, blk, GEMM_SMEM>>>(Wkr, Wqr, nullptr, MTp, nullptr,
                                        HID, 256, HID,
                                        256, 256, (size_t)HID * HID, 0, 1.f);

    // L2: MT = fp16(sum of partials)
    reduce_mt<<<HID * HID / 1024, blk>>>(MTp, MT);

    // L3: w2 = Wk @ bq
    gemv_w2<<<HID, blk>>>(Wk, bq, w2);

    // L4: X -> fp16 + v = (X @ w2) * scale
    to_half_v<<<MTOT, blk>>>(X, w2, Xh, v);

    // L5: V^T = Wv^T @ X^T (per batch), ROW bias, fp16 out
    dim3 gv(SEQ / 128, HID / 128, BATCH);
    gemm_h<1,2><<<gv, blk, GEMM_SMEM>>>(Wvh, Xh, bv, nullptr, Vth,
                                        SEQ, HID, HID,
                                        0, (size_t)SEQ * HID, (size_t)HID * SEQ,
                                        0, 1.f);

    // L6: A = X @ MT^T  (fp16 out)
    dim3 ga(HID / 128, MTOT / 128, 1);
    gemm_h<1,0><<<ga, blk, GEMM_SMEM>>>(Xh, MT, nullptr, nullptr, Ah,
                                        HID, HID, HID, 0, 0, 0, 0, 1.f);

    // L7: scores = scale * (A @ X^T) + v_col (batched; u,c cancel in softmax)
    dim3 gs(SEQ / 128, SEQ / 128, BATCH);
    gemm_h<1,1><<<gs, blk, GEMM_SMEM>>>(Ah, Xh, v, nullptr, Ssc,
                                        SEQ, HID, HID,
                                        (size_t)SEQ * HID, (size_t)SEQ * HID,
                                        (size_t)SEQ * SEQ, SEQ, SCALE);

    // L8: softmax fp16 -> fp16
    softmax_h<<<BATCH * SEQ, blk>>>(Ssc, Sh);

    // L9: context = attn @ V (batched, K=2048) -> fp16
    dim3 gc(HID / 128, SEQ / 128, BATCH);
    gemm_h<1,0><<<gc, blk, GEMM_SMEM>>>(Sh, Vth, nullptr, nullptr, Ch,
                                        HID, SEQ, SEQ,
                                        (size_t)SEQ * SEQ, (size_t)HID * SEQ,
                                        (size_t)SEQ * HID, 0, 1.f);

    // L10: y = context @ Wh + bh -> d_out fp32
    dim3 go(HID / 128, MTOT / 128, 1);
    gemm_h<0,1><<<go, blk, GEMM_SMEM>>>(Ch, Whh, bh, out, nullptr,
                                        HID, HID, HID, 0, 0, 0, 0, 1.f);
}